// round 14
// baseline (speedup 1.0000x reference)
#include <cuda_runtime.h>
#include <float.h>
#include <math.h>

#define B 8
#define N 2048
#define PTS (B*N)          // 16384
#define KNN 20
#define FEAT 512
#define OMAX 256
#define EPSV 1e-5f
#define NB 16              // N/128 tile count

// ---------------- scratch (static device allocations) ----------------
__device__ float d_dist[(size_t)PTS * N];        // 134 MB
__device__ float d_xx[PTS];
__device__ int   d_idx[PTS * KNN];
__device__ float d_feat[(size_t)PTS * FEAT];
__device__ float d_s[(size_t)PTS * OMAX];
__device__ float d_t[(size_t)PTS * OMAX];
__device__ float d_maxg[(size_t)PTS * OMAX];
__device__ float d_ming[(size_t)PTS * OMAX];
__device__ float d_acc_s[OMAX], d_acc_s2[OMAX], d_acc_cr[OMAX], d_acc_t[OMAX], d_acc_t2[OMAX];
__device__ float d_rho[OMAX], d_shift[OMAX];
__device__ float d_poolmax[B * 8 * FEAT], d_poolsum[B * 8 * FEAT];

// ---------------- kernels ----------------

// squared norms per point; block 0 also zeroes the per-layer accumulators
__global__ void xx_kernel(const float* x, int stride, int off, int C) {
    const float* xp = x ? x : d_feat;
    int p = blockIdx.x * blockDim.x + threadIdx.x;
    if (blockIdx.x == 0) {
        int i = threadIdx.x;
        if (i < OMAX) {
            d_acc_s[i] = 0.f; d_acc_s2[i] = 0.f; d_acc_cr[i] = 0.f;
            d_acc_t[i] = 0.f; d_acc_t2[i] = 0.f;
        }
    }
    if (p >= PTS) return;
    const float* r = xp + (size_t)p * stride + off;
    float s = 0.f;
    for (int c = 0; c < C; c++) { float v = r[c]; s = fmaf(v, v, s); }
    d_xx[p] = s;
}

// dist (R9 proven): symmetric upper-tri 128x128 block pairs; 512 threads,
// 8x4 micro-tile, register-prefetch double buffering.
__global__ void __launch_bounds__(512, 2)
dist_kernel(const float* __restrict__ x, int stride, int off, int C) {
    const float* xp = x ? x : d_feat;
    int b = blockIdx.x;
    int p = blockIdx.y;
    int pi = 0;
    while (p >= NB - pi) { p -= NB - pi; pi++; }
    int pj = pi + p;
    int n0 = pi * 128, m0 = pj * 128;

    __shared__ float As[16][132];
    __shared__ float Bs[16][132];
    __shared__ float xn_s[128], xm_s[128];

    int tid = threadIdx.x;            // 512 threads
    int tx = tid & 31, ty = tid >> 5;
    if (tid < 128) xn_s[tid] = d_xx[b * N + n0 + tid];
    else if (tid < 256) xm_s[tid - 128] = d_xx[b * N + m0 + tid - 128];

    float acc[8][4];
#pragma unroll
    for (int i = 0; i < 8; i++)
#pragma unroll
        for (int j = 0; j < 4; j++) acc[i][j] = 0.f;

    bool diag = (pi == pj);
    float pa[4], pb[4];
    int lr[4], lc[4];
#pragma unroll
    for (int it = 0; it < 4; it++) {
        int l = tid + it * 512;
        lr[it] = l >> 4;
        lc[it] = l & 15;
    }
#pragma unroll
    for (int it = 0; it < 4; it++) {
        int c = lc[it];
        pa[it] = (c < C) ? xp[(size_t)(b * N + n0 + lr[it]) * stride + off + c] : 0.f;
        pb[it] = (!diag && c < C) ? xp[(size_t)(b * N + m0 + lr[it]) * stride + off + c] : 0.f;
    }

    for (int c0 = 0; c0 < C; c0 += 16) {
#pragma unroll
        for (int it = 0; it < 4; it++) {
            As[lc[it]][lr[it]] = pa[it];
            if (!diag) Bs[lc[it]][lr[it]] = pb[it];
        }
        __syncthreads();
        if (c0 + 16 < C) {
#pragma unroll
            for (int it = 0; it < 4; it++) {
                int c = c0 + 16 + lc[it];
                pa[it] = (c < C) ? xp[(size_t)(b * N + n0 + lr[it]) * stride + off + c] : 0.f;
                pb[it] = (!diag && c < C) ? xp[(size_t)(b * N + m0 + lr[it]) * stride + off + c] : 0.f;
            }
        }
        const float (*Bp)[132] = diag ? As : Bs;
#pragma unroll
        for (int kk = 0; kk < 16; kk++) {
            float4 a0 = *(const float4*)&As[kk][ty * 4];
            float4 a1 = *(const float4*)&As[kk][64 + ty * 4];
            float4 bf = *(const float4*)&Bp[kk][tx * 4];
            float a[8] = {a0.x, a0.y, a0.z, a0.w, a1.x, a1.y, a1.z, a1.w};
            float bb[4] = {bf.x, bf.y, bf.z, bf.w};
#pragma unroll
            for (int i = 0; i < 8; i++)
#pragma unroll
                for (int j = 0; j < 4; j++) acc[i][j] = fmaf(a[i], bb[j], acc[i][j]);
        }
        __syncthreads();
    }

#pragma unroll
    for (int i = 0; i < 8; i++) {
        int nl = (i < 4) ? (ty * 4 + i) : (64 + ty * 4 + i - 4);
        float xn = xn_s[nl];
        float* orow = d_dist + (size_t)(b * N + n0 + nl) * N + m0;
        float4 v;
        v.x = xn + xm_s[tx * 4 + 0] - 2.f * acc[i][0];
        v.y = xn + xm_s[tx * 4 + 1] - 2.f * acc[i][1];
        v.z = xn + xm_s[tx * 4 + 2] - 2.f * acc[i][2];
        v.w = xn + xm_s[tx * 4 + 3] - 2.f * acc[i][3];
        *(float4*)(orow + tx * 4) = v;
    }
    if (!diag) {
#pragma unroll
        for (int j = 0; j < 4; j++) {
            int ml = tx * 4 + j;
            float xm = xm_s[ml];
            float* orow = d_dist + (size_t)(b * N + m0 + ml) * N + n0;
            float4 v0, v1;
            v0.x = xn_s[ty * 4 + 0] + xm - 2.f * acc[0][j];
            v0.y = xn_s[ty * 4 + 1] + xm - 2.f * acc[1][j];
            v0.z = xn_s[ty * 4 + 2] + xm - 2.f * acc[2][j];
            v0.w = xn_s[ty * 4 + 3] + xm - 2.f * acc[3][j];
            v1.x = xn_s[64 + ty * 4 + 0] + xm - 2.f * acc[4][j];
            v1.y = xn_s[64 + ty * 4 + 1] + xm - 2.f * acc[5][j];
            v1.z = xn_s[64 + ty * 4 + 2] + xm - 2.f * acc[6][j];
            v1.w = xn_s[64 + ty * 4 + 3] + xm - 2.f * acc[7][j];
            *(float4*)(orow + ty * 4) = v0;
            *(float4*)(orow + 64 + ty * 4) = v1;
        }
    }
}

// select: warp per row, ZERO smem. Each lane keeps an exact sorted top-8
// (lexicographic (v,idx)) of its 64-element strip in registers (lane-private
// insertions). Merge: 20 pops via warp pair-min reduction; if a lane's 8
// entries are exhausted it refills exactly by rescanning its strip (rare).
__global__ void select_kernel() {
    const unsigned FULL = 0xffffffffu;
    int warp = threadIdx.x >> 5, lane = threadIdx.x & 31;
    int pt = blockIdx.x * 8 + warp;
    const float4* dr4 = (const float4*)(d_dist + (size_t)pt * N);

    float sv[8];
    int   si[8];
#pragma unroll
    for (int q = 0; q < 8; q++) { sv[q] = FLT_MAX; si[q] = 0x7fffffff; }

    // ---- streaming phase: lane-private sorted top-8 insertion ----
#pragma unroll 4
    for (int it = 0; it < 16; it++) {
        float4 v = dr4[it * 32 + lane];
        int base = (it * 32 + lane) * 4;
        float cv4[4] = {v.x, v.y, v.z, v.w};
#pragma unroll
        for (int j = 0; j < 4; j++) {
            float cv = cv4[j];
            int ci = base + j;
            if (cv < sv[7] || (cv == sv[7] && ci < si[7])) {
                bool placed = false;
#pragma unroll
                for (int q = 7; q > 0; q--) {
                    if (!placed) {
                        if (cv < sv[q - 1] || (cv == sv[q - 1] && ci < si[q - 1])) {
                            sv[q] = sv[q - 1]; si[q] = si[q - 1];
                        } else {
                            sv[q] = cv; si[q] = ci; placed = true;
                        }
                    }
                }
                if (!placed) { sv[0] = cv; si[0] = ci; }
            }
        }
    }

    // ---- merge phase: 20 pops of global lexicographic min ----
    float curv = sv[0]; int curi = si[0];
    int pops = 0;
    float lastv = 0.f; int lasti = 0;
    int* ip = d_idx + pt * KNN;
    for (int sel = 0; sel < KNN; sel++) {
        float wv = curv; int wi = curi;
#pragma unroll
        for (int s = 16; s > 0; s >>= 1) {
            float ov = __shfl_xor_sync(FULL, wv, s);
            int   oi = __shfl_xor_sync(FULL, wi, s);
            if (ov < wv || (ov == wv && oi < wi)) { wv = ov; wi = oi; }
        }
        if (lane == 0) ip[sel] = wi;
        if (curv == wv && curi == wi) {       // this lane is the winner
            pops++;
            lastv = curv; lasti = curi;
            if (pops < 8) {
                curv = sv[1]; curi = si[1];
#pragma unroll
                for (int q = 1; q < 7; q++) { sv[q] = sv[q + 1]; si[q] = si[q + 1]; }
                sv[7] = FLT_MAX; si[7] = 0x7fffffff;
            } else {
                // exact refill: smallest pair strictly greater than (lastv,lasti)
                float bv = FLT_MAX; int bi = 0x7fffffff;
                for (int it = 0; it < 16; it++) {
                    float4 v = dr4[it * 32 + lane];
                    int base = (it * 32 + lane) * 4;
                    float cv4[4] = {v.x, v.y, v.z, v.w};
#pragma unroll
                    for (int j = 0; j < 4; j++) {
                        float cv = cv4[j];
                        int ci = base + j;
                        bool gt_last = (cv > lastv) || (cv == lastv && ci > lasti);
                        bool lt_best = (cv < bv) || (cv == bv && ci < bi);
                        if (gt_last && lt_best) { bv = cv; bi = ci; }
                    }
                }
                curv = bv; curi = bi;
            }
        }
    }
}

// st: register-tiled dual GEMM. Block = 64 points x 64 outs, 4x4 per thread.
// Stats reduced in smem first -> ONE global atomic per channel per block.
__global__ void st_kernel(const float* __restrict__ x, int stride, int off, int C,
                          int O, const float* __restrict__ W) {
    const float* xp = x ? x : d_feat;
    int pt0 = blockIdx.x * 64;
    int o0 = blockIdx.y * 64;
    __shared__ float xs[16][68];
    __shared__ float w1s[16][68];
    __shared__ float wds[16][68];
    __shared__ float rts[16][64];
    __shared__ float rts2[16][64];
    int tid = threadIdx.x;
    int tx = tid & 15, ty = tid >> 4;
    float accs[4][4], acct[4][4];
#pragma unroll
    for (int i = 0; i < 4; i++)
#pragma unroll
        for (int j = 0; j < 4; j++) { accs[i][j] = 0.f; acct[i][j] = 0.f; }

    for (int c0 = 0; c0 < C; c0 += 16) {
        for (int l = tid; l < 1024; l += 256) {
            int r = l >> 4, cc = l & 15;
            int c = c0 + cc;
            xs[cc][r] = (c < C) ? xp[(size_t)(pt0 + r) * stride + off + c] : 0.f;
            float a = 0.f, d = 0.f;
            if (c < C) {
                a = W[(size_t)(o0 + r) * 2 * C + c];
                d = W[(size_t)(o0 + r) * 2 * C + C + c] - a;
            }
            w1s[cc][r] = a;
            wds[cc][r] = d;
        }
        __syncthreads();
#pragma unroll
        for (int kk = 0; kk < 16; kk++) {
            float4 xa = *(const float4*)&xs[kk][ty * 4];
            float4 wb = *(const float4*)&w1s[kk][tx * 4];
            float4 wd = *(const float4*)&wds[kk][tx * 4];
            float a[4] = {xa.x, xa.y, xa.z, xa.w};
            float w1v[4] = {wb.x, wb.y, wb.z, wb.w};
            float wdv[4] = {wd.x, wd.y, wd.z, wd.w};
#pragma unroll
            for (int i = 0; i < 4; i++)
#pragma unroll
                for (int j = 0; j < 4; j++) {
                    accs[i][j] = fmaf(a[i], w1v[j], accs[i][j]);
                    acct[i][j] = fmaf(a[i], wdv[j], acct[i][j]);
                }
        }
        __syncthreads();
    }

    float ts[4] = {0.f, 0.f, 0.f, 0.f}, ts2[4] = {0.f, 0.f, 0.f, 0.f};
#pragma unroll
    for (int i = 0; i < 4; i++) {
        size_t base = (size_t)(pt0 + ty * 4 + i) * O + o0 + tx * 4;
        float4 sv = {accs[i][0], accs[i][1], accs[i][2], accs[i][3]};
        float4 tv = {acct[i][0], acct[i][1], acct[i][2], acct[i][3]};
        *(float4*)&d_s[base] = sv;
        *(float4*)&d_t[base] = tv;
#pragma unroll
        for (int j = 0; j < 4; j++) {
            ts[j] += acct[i][j];
            ts2[j] = fmaf(acct[i][j], acct[i][j], ts2[j]);
        }
    }
#pragma unroll
    for (int j = 0; j < 4; j++) {
        rts[ty][tx * 4 + j] = ts[j];
        rts2[ty][tx * 4 + j] = ts2[j];
    }
    __syncthreads();
    if (tid < 64) {
        float a = 0.f, a2 = 0.f;
#pragma unroll
        for (int r = 0; r < 16; r++) { a += rts[r][tid]; a2 += rts2[r][tid]; }
        atomicAdd(&d_acc_t[o0 + tid], a);
        atomicAdd(&d_acc_t2[o0 + tid], a2);
    }
}

// gather: thread owns 4 consecutive channels (float4); 64 points per block.
// Stats reduced in smem first -> ONE global atomic per channel per block.
__global__ void gather_kernel(int O) {
    __shared__ float ssum[256 * 4];
    __shared__ float ssq[256 * 4];
    __shared__ float scr[256 * 4];
    int Q = O >> 2;
    int tid = threadIdx.x;
    int q = tid & (Q - 1);
    int sub = tid / Q;
    int nsub = 256 / Q;
    int o = q * 4;
    int pt0 = blockIdx.x * 64;
    float sum[4] = {0,0,0,0}, sq[4] = {0,0,0,0}, cross[4] = {0,0,0,0};
    for (int p = sub; p < 64; p += nsub) {
        int pt = pt0 + p;
        int bb = pt >> 11;
        const int* ip = d_idx + pt * KNN;
        float psum[4] = {0,0,0,0}, psq[4] = {0,0,0,0};
        float pmx[4] = {-FLT_MAX,-FLT_MAX,-FLT_MAX,-FLT_MAX};
        float pmn[4] = {FLT_MAX,FLT_MAX,FLT_MAX,FLT_MAX};
#pragma unroll
        for (int k = 0; k < KNN; k++) {
            int m = ip[k];
            float4 v = *(const float4*)&d_s[(size_t)((bb << 11) + m) * O + o];
            float vv[4] = {v.x, v.y, v.z, v.w};
#pragma unroll
            for (int j = 0; j < 4; j++) {
                psum[j] += vv[j];
                psq[j] = fmaf(vv[j], vv[j], psq[j]);
                pmx[j] = fmaxf(pmx[j], vv[j]);
                pmn[j] = fminf(pmn[j], vv[j]);
            }
        }
        float4 tv = *(const float4*)&d_t[(size_t)pt * O + o];
        float tvv[4] = {tv.x, tv.y, tv.z, tv.w};
#pragma unroll
        for (int j = 0; j < 4; j++) {
            sum[j] += psum[j];
            sq[j] += psq[j];
            cross[j] = fmaf(tvv[j], psum[j], cross[j]);
        }
        float4 mx4 = {pmx[0], pmx[1], pmx[2], pmx[3]};
        float4 mn4 = {pmn[0], pmn[1], pmn[2], pmn[3]};
        *(float4*)&d_maxg[(size_t)pt * O + o] = mx4;
        *(float4*)&d_ming[(size_t)pt * O + o] = mn4;
    }
#pragma unroll
    for (int j = 0; j < 4; j++) {
        ssum[tid * 4 + j] = sum[j];
        ssq[tid * 4 + j] = sq[j];
        scr[tid * 4 + j] = cross[j];
    }
    __syncthreads();
    if (tid < O) {
        int qq = tid >> 2, jj = tid & 3;
        float a = 0.f, a2 = 0.f, a3 = 0.f;
        for (int s = 0; s < nsub; s++) {
            int t = s * Q + qq;
            a += ssum[t * 4 + jj];
            a2 += ssq[t * 4 + jj];
            a3 += scr[t * 4 + jj];
        }
        atomicAdd(&d_acc_s[tid], a);
        atomicAdd(&d_acc_s2[tid], a2);
        atomicAdd(&d_acc_cr[tid], a3);
    }
}

__global__ void bn_kernel(int O, const float* gamma, const float* beta) {
    int o = threadIdx.x;
    if (o >= O) return;
    const float cnt = (float)PTS * (float)KNN;
    float mean = (d_acc_s[o] + (float)KNN * d_acc_t[o]) / cnt;
    float e2 = (d_acc_s2[o] + 2.f * d_acc_cr[o] + (float)KNN * d_acc_t2[o]) / cnt;
    float var = e2 - mean * mean;
    float inv = rsqrtf(var + EPSV);
    float rho = gamma[o] * inv;
    d_rho[o] = rho;
    d_shift[o] = beta[o] - mean * rho;
}

// apply: float4 over channels
__global__ void apply_kernel(int O, int off) {
    int e4 = blockIdx.x * 256 + threadIdx.x;
    int total = PTS * O / 4;
    if (e4 >= total) return;
    int qpr = O >> 2;
    int o = (e4 & (qpr - 1)) * 4;
    int pt = e4 / qpr;
    size_t base = (size_t)pt * O + o;
    float4 r4 = *(const float4*)&d_rho[o];
    float4 sh = *(const float4*)&d_shift[o];
    float4 t4 = *(const float4*)&d_t[base];
    float4 mx = *(const float4*)&d_maxg[base];
    float4 mn = *(const float4*)&d_ming[base];
    float rr[4] = {r4.x, r4.y, r4.z, r4.w};
    float ss[4] = {sh.x, sh.y, sh.z, sh.w};
    float tt[4] = {t4.x, t4.y, t4.z, t4.w};
    float gx[4] = {mx.x, mx.y, mx.z, mx.w};
    float gn[4] = {mn.x, mn.y, mn.z, mn.w};
    float out[4];
#pragma unroll
    for (int j = 0; j < 4; j++) {
        float base_v = tt[j] + (rr[j] >= 0.f ? gx[j] : gn[j]);
        out[j] = fmaxf(fmaf(rr[j], base_v, ss[j]), 0.f);
    }
    float4 o4 = {out[0], out[1], out[2], out[3]};
    *(float4*)&d_feat[(size_t)pt * FEAT + off + o] = o4;
}

__global__ void pool_kernel() {
    int b = blockIdx.x, st = blockIdx.y;
    int c = threadIdx.x;
    float mx = -FLT_MAX, sm = 0.f;
    int n0 = st * 256;
    for (int n = n0; n < n0 + 256; n++) {
        float v = d_feat[(size_t)(b * N + n) * FEAT + c];
        mx = fmaxf(mx, v);
        sm += v;
    }
    d_poolmax[(b * 8 + st) * FEAT + c] = mx;
    d_poolsum[(b * 8 + st) * FEAT + c] = sm;
}

__global__ void head_kernel(const float* fc1_w, const float* fc1_b,
                            const float* ln1_g, const float* ln1_b,
                            const float* fc2_w, const float* fc2_b,
                            const float* ln2_g, const float* ln2_b,
                            float* out) {
    __shared__ float g[1024];
    __shared__ float h[512];
    __shared__ float red[256];
    __shared__ float red2[256];
    int b = blockIdx.x, tid = threadIdx.x;
    for (int c = tid; c < 512; c += 256) {
        float mx = -FLT_MAX, sm = 0.f;
        for (int st = 0; st < 8; st++) {
            mx = fmaxf(mx, d_poolmax[(b * 8 + st) * FEAT + c]);
            sm += d_poolsum[(b * 8 + st) * FEAT + c];
        }
        g[c] = mx;
        g[512 + c] = sm * (1.f / (float)N);
    }
    __syncthreads();
    for (int j = tid; j < 512; j += 256) {
        float acc = fc1_b[j];
        const float* wr = fc1_w + (size_t)j * 1024;
        for (int i = 0; i < 1024; i++) acc = fmaf(g[i], wr[i], acc);
        h[j] = acc;
    }
    __syncthreads();
    {
        float a = h[tid], bb = h[tid + 256];
        red[tid] = a + bb;
        red2[tid] = a * a + bb * bb;
    }
    __syncthreads();
    for (int s = 128; s > 0; s >>= 1) {
        if (tid < s) { red[tid] += red[tid + s]; red2[tid] += red2[tid + s]; }
        __syncthreads();
    }
    float mu = red[0] * (1.f / 512.f);
    float var = red2[0] * (1.f / 512.f) - mu * mu;
    float inv = rsqrtf(var + EPSV);
    __syncthreads();
    for (int j = tid; j < 512; j += 256)
        h[j] = fmaxf(0.f, (h[j] - mu) * inv * ln1_g[j] + ln1_b[j]);
    __syncthreads();
    float z = fc2_b[tid];
    {
        const float* wr = fc2_w + (size_t)tid * 512;
        for (int i = 0; i < 512; i++) z = fmaf(h[i], wr[i], z);
    }
    red[tid] = z;
    red2[tid] = z * z;
    __syncthreads();
    for (int s = 128; s > 0; s >>= 1) {
        if (tid < s) { red[tid] += red[tid + s]; red2[tid] += red2[tid + s]; }
        __syncthreads();
    }
    float mu2 = red[0] * (1.f / 256.f);
    float var2 = red2[0] * (1.f / 256.f) - mu2 * mu2;
    float inv2 = rsqrtf(var2 + EPSV);
    out[b * 256 + tid] = (z - mu2) * inv2 * ln2_g[tid] + ln2_b[tid];
}

// ---------------- launch ----------------

extern "C" void kernel_launch(void* const* d_in, const int* in_sizes, int n_in,
                              void* d_out, int out_size) {
    (void)in_sizes; (void)n_in; (void)out_size;
    const float* points = (const float*)d_in[0];
    const float* Wl[4]  = {(const float*)d_in[1], (const float*)d_in[4],
                           (const float*)d_in[7], (const float*)d_in[10]};
    const float* gl[4]  = {(const float*)d_in[2], (const float*)d_in[5],
                           (const float*)d_in[8], (const float*)d_in[11]};
    const float* bl[4]  = {(const float*)d_in[3], (const float*)d_in[6],
                           (const float*)d_in[9], (const float*)d_in[12]};
    const float* fc1_w = (const float*)d_in[13];
    const float* fc1_b = (const float*)d_in[14];
    const float* ln1_g = (const float*)d_in[15];
    const float* ln1_b = (const float*)d_in[16];
    const float* fc2_w = (const float*)d_in[17];
    const float* fc2_b = (const float*)d_in[18];
    const float* ln2_g = (const float*)d_in[19];
    const float* ln2_b = (const float*)d_in[20];

    const int Cs[4]     = {3, 64, 64, 128};
    const int Os[4]     = {64, 64, 128, 256};
    const int offin[4]  = {0, 0, 64, 128};
    const int offout[4] = {0, 64, 128, 256};
    const int NPAIRS = NB * (NB + 1) / 2;   // 136

    for (int l = 0; l < 4; l++) {
        const float* xin = (l == 0) ? points : nullptr;
        int stride = (l == 0) ? 3 : FEAT;
        int C = Cs[l], O = Os[l];

        xx_kernel<<<(PTS + 255) / 256, 256>>>(xin, stride, offin[l], C);
        dist_kernel<<<dim3(B, NPAIRS), 512>>>(xin, stride, offin[l], C);
        select_kernel<<<PTS / 8, 256>>>();
        st_kernel<<<dim3(PTS / 64, O / 64), 256>>>(xin, stride, offin[l], C, O, Wl[l]);
        gather_kernel<<<PTS / 64, 256>>>(O);
        bn_kernel<<<1, O>>>(O, gl[l], bl[l]);
        apply_kernel<<<(PTS * O / 4 + 255) / 256, 256>>>(O, offout[l]);
    }

    pool_kernel<<<dim3(B, 8), 512>>>();
    head_kernel<<<B, 256>>>(fc1_w, fc1_b, ln1_g, ln1_b,
                            fc2_w, fc2_b, ln2_g, ln2_b, (float*)d_out);
}

// round 15
// speedup vs baseline: 1.6523x; 1.6523x over previous
#include <cuda_runtime.h>
#include <float.h>
#include <math.h>

#define B 8
#define N 2048
#define PTS (B*N)          // 16384
#define KNN 20
#define FEAT 512
#define OMAX 256
#define EPSV 1e-5f
#define NB 16              // N/128 tile count

// ---------------- scratch (static device allocations) ----------------
__device__ float d_dist[(size_t)PTS * N];        // 134 MB
__device__ float d_xx[PTS];
__device__ int   d_idx[PTS * KNN];
__device__ float d_feat[(size_t)PTS * FEAT];
__device__ float d_s[(size_t)PTS * OMAX];
__device__ float d_t[(size_t)PTS * OMAX];
__device__ float d_maxg[(size_t)PTS * OMAX];
__device__ float d_ming[(size_t)PTS * OMAX];
__device__ float d_acc_s[OMAX], d_acc_s2[OMAX], d_acc_cr[OMAX], d_acc_t[OMAX], d_acc_t2[OMAX];
__device__ float d_rho[OMAX], d_shift[OMAX];
__device__ float d_poolmax[B * 8 * FEAT], d_poolsum[B * 8 * FEAT];

// ---------------- kernels ----------------

// squared norms per point; block 0 also zeroes the per-layer accumulators
__global__ void xx_kernel(const float* x, int stride, int off, int C) {
    const float* xp = x ? x : d_feat;
    int p = blockIdx.x * blockDim.x + threadIdx.x;
    if (blockIdx.x == 0) {
        int i = threadIdx.x;
        if (i < OMAX) {
            d_acc_s[i] = 0.f; d_acc_s2[i] = 0.f; d_acc_cr[i] = 0.f;
            d_acc_t[i] = 0.f; d_acc_t2[i] = 0.f;
        }
    }
    if (p >= PTS) return;
    const float* r = xp + (size_t)p * stride + off;
    float s = 0.f;
    for (int c = 0; c < C; c++) { float v = r[c]; s = fmaf(v, v, s); }
    d_xx[p] = s;
}

// dist: symmetric upper-tri 128x128 block pairs; 512 threads, 8x4 micro-tile,
// register-prefetch double buffering of the k-panels.
__global__ void __launch_bounds__(512, 2)
dist_kernel(const float* __restrict__ x, int stride, int off, int C) {
    const float* xp = x ? x : d_feat;
    int b = blockIdx.x;
    int p = blockIdx.y;
    int pi = 0;
    while (p >= NB - pi) { p -= NB - pi; pi++; }
    int pj = pi + p;
    int n0 = pi * 128, m0 = pj * 128;

    __shared__ float As[16][132];
    __shared__ float Bs[16][132];
    __shared__ float xn_s[128], xm_s[128];

    int tid = threadIdx.x;            // 512 threads
    int tx = tid & 31, ty = tid >> 5;
    if (tid < 128) xn_s[tid] = d_xx[b * N + n0 + tid];
    else if (tid < 256) xm_s[tid - 128] = d_xx[b * N + m0 + tid - 128];

    float acc[8][4];
#pragma unroll
    for (int i = 0; i < 8; i++)
#pragma unroll
        for (int j = 0; j < 4; j++) acc[i][j] = 0.f;

    bool diag = (pi == pj);
    // prefetch registers: 4 elements each for A and B per panel
    float pa[4], pb[4];
    int lr[4], lc[4];
#pragma unroll
    for (int it = 0; it < 4; it++) {
        int l = tid + it * 512;
        lr[it] = l >> 4;
        lc[it] = l & 15;
    }
    // load panel 0
#pragma unroll
    for (int it = 0; it < 4; it++) {
        int c = lc[it];
        pa[it] = (c < C) ? xp[(size_t)(b * N + n0 + lr[it]) * stride + off + c] : 0.f;
        pb[it] = (!diag && c < C) ? xp[(size_t)(b * N + m0 + lr[it]) * stride + off + c] : 0.f;
    }

    for (int c0 = 0; c0 < C; c0 += 16) {
        // store prefetched panel to smem
#pragma unroll
        for (int it = 0; it < 4; it++) {
            As[lc[it]][lr[it]] = pa[it];
            if (!diag) Bs[lc[it]][lr[it]] = pb[it];
        }
        __syncthreads();
        // issue next panel's loads (latency hidden by compute below)
        if (c0 + 16 < C) {
#pragma unroll
            for (int it = 0; it < 4; it++) {
                int c = c0 + 16 + lc[it];
                pa[it] = (c < C) ? xp[(size_t)(b * N + n0 + lr[it]) * stride + off + c] : 0.f;
                pb[it] = (!diag && c < C) ? xp[(size_t)(b * N + m0 + lr[it]) * stride + off + c] : 0.f;
            }
        }
        const float (*Bp)[132] = diag ? As : Bs;
#pragma unroll
        for (int kk = 0; kk < 16; kk++) {
            float4 a0 = *(const float4*)&As[kk][ty * 4];
            float4 a1 = *(const float4*)&As[kk][64 + ty * 4];
            float4 bf = *(const float4*)&Bp[kk][tx * 4];
            float a[8] = {a0.x, a0.y, a0.z, a0.w, a1.x, a1.y, a1.z, a1.w};
            float bb[4] = {bf.x, bf.y, bf.z, bf.w};
#pragma unroll
            for (int i = 0; i < 8; i++)
#pragma unroll
                for (int j = 0; j < 4; j++) acc[i][j] = fmaf(a[i], bb[j], acc[i][j]);
        }
        __syncthreads();
    }

#pragma unroll
    for (int i = 0; i < 8; i++) {
        int nl = (i < 4) ? (ty * 4 + i) : (64 + ty * 4 + i - 4);
        float xn = xn_s[nl];
        float* orow = d_dist + (size_t)(b * N + n0 + nl) * N + m0;
        float4 v;
        v.x = xn + xm_s[tx * 4 + 0] - 2.f * acc[i][0];
        v.y = xn + xm_s[tx * 4 + 1] - 2.f * acc[i][1];
        v.z = xn + xm_s[tx * 4 + 2] - 2.f * acc[i][2];
        v.w = xn + xm_s[tx * 4 + 3] - 2.f * acc[i][3];
        *(float4*)(orow + tx * 4) = v;
    }
    if (!diag) {
#pragma unroll
        for (int j = 0; j < 4; j++) {
            int ml = tx * 4 + j;
            float xm = xm_s[ml];
            float* orow = d_dist + (size_t)(b * N + m0 + ml) * N + n0;
            float4 v0, v1;
            v0.x = xn_s[ty * 4 + 0] + xm - 2.f * acc[0][j];
            v0.y = xn_s[ty * 4 + 1] + xm - 2.f * acc[1][j];
            v0.z = xn_s[ty * 4 + 2] + xm - 2.f * acc[2][j];
            v0.w = xn_s[ty * 4 + 3] + xm - 2.f * acc[3][j];
            v1.x = xn_s[64 + ty * 4 + 0] + xm - 2.f * acc[4][j];
            v1.y = xn_s[64 + ty * 4 + 1] + xm - 2.f * acc[5][j];
            v1.z = xn_s[64 + ty * 4 + 2] + xm - 2.f * acc[6][j];
            v1.w = xn_s[64 + ty * 4 + 3] + xm - 2.f * acc[7][j];
            *(float4*)(orow + ty * 4) = v0;
            *(float4*)(orow + 64 + ty * 4) = v1;
        }
    }
}

// per-row top-KNN: warp per row; value-only fminf reductions + ballot for index.
__global__ void select_kernel() {
    __shared__ float rows[4][64][33];
    int warp = threadIdx.x >> 5, lane = threadIdx.x & 31;
    int pt = blockIdx.x * 4 + warp;
    float (*row)[33] = rows[warp];
    const float4* dr4 = (const float4*)(d_dist + (size_t)pt * N);
#pragma unroll
    for (int it = 0; it < 16; it++) {
        int i4 = lane + 32 * it;
        float4 v = dr4[i4];
        int e = 4 * i4;
        row[e >> 5][e & 31] = v.x;
        row[(e + 1) >> 5][(e + 1) & 31] = v.y;
        row[(e + 2) >> 5][(e + 2) & 31] = v.z;
        row[(e + 3) >> 5][(e + 3) & 31] = v.w;
    }
    __syncwarp();

    float bv = FLT_MAX; int bi = 0;
#pragma unroll 8
    for (int m = 0; m < 64; m++) {
        float v = row[m][lane];
        if (v < bv) { bv = v; bi = lane + 32 * m; }
    }
    int* ip = d_idx + pt * KNN;
    for (int sel = 0; sel < KNN; sel++) {
        // min value across lanes
        float mv = bv;
#pragma unroll
        for (int s = 16; s > 0; s >>= 1)
            mv = fminf(mv, __shfl_xor_sync(0xffffffff, mv, s));
        unsigned mask = __ballot_sync(0xffffffff, bv == mv);
        int ol = __ffs(mask) - 1;                      // owner lane
        int mi = __shfl_sync(0xffffffff, bi, ol);
        if (lane == 0) ip[sel] = mi;
        if (lane == ol) row[mi >> 5][ol] = FLT_MAX;
        __syncwarp();
        // cooperative rescan of owner strip (elements ol + 32*m)
        float v0 = row[lane][ol];
        float v1 = row[lane + 32][ol];
        float cand = fminf(v0, v1);
        int candi = (v0 <= v1) ? (ol + 32 * lane) : (ol + 32 * (lane + 32));
        float nv = cand;
#pragma unroll
        for (int s = 16; s > 0; s >>= 1)
            nv = fminf(nv, __shfl_xor_sync(0xffffffff, nv, s));
        unsigned m2 = __ballot_sync(0xffffffff, cand == nv);
        int l2 = __ffs(m2) - 1;
        int ni = __shfl_sync(0xffffffff, candi, l2);
        if (lane == ol) { bv = nv; bi = ni; }
        __syncwarp();
    }
}

// st: register-tiled dual GEMM. Block = 64 points x 64 outs, 4x4 per thread.
// Stats reduced in smem first -> ONE global atomic per channel per block.
__global__ void st_kernel(const float* __restrict__ x, int stride, int off, int C,
                          int O, const float* __restrict__ W) {
    const float* xp = x ? x : d_feat;
    int pt0 = blockIdx.x * 64;
    int o0 = blockIdx.y * 64;
    __shared__ float xs[16][68];
    __shared__ float w1s[16][68];
    __shared__ float wds[16][68];
    __shared__ float rts[16][64];
    __shared__ float rts2[16][64];
    int tid = threadIdx.x;
    int tx = tid & 15, ty = tid >> 4;
    float accs[4][4], acct[4][4];
#pragma unroll
    for (int i = 0; i < 4; i++)
#pragma unroll
        for (int j = 0; j < 4; j++) { accs[i][j] = 0.f; acct[i][j] = 0.f; }

    for (int c0 = 0; c0 < C; c0 += 16) {
        for (int l = tid; l < 1024; l += 256) {
            int r = l >> 4, cc = l & 15;
            int c = c0 + cc;
            xs[cc][r] = (c < C) ? xp[(size_t)(pt0 + r) * stride + off + c] : 0.f;
            float a = 0.f, d = 0.f;
            if (c < C) {
                a = W[(size_t)(o0 + r) * 2 * C + c];
                d = W[(size_t)(o0 + r) * 2 * C + C + c] - a;
            }
            w1s[cc][r] = a;
            wds[cc][r] = d;
        }
        __syncthreads();
#pragma unroll
        for (int kk = 0; kk < 16; kk++) {
            float4 xa = *(const float4*)&xs[kk][ty * 4];
            float4 wb = *(const float4*)&w1s[kk][tx * 4];
            float4 wd = *(const float4*)&wds[kk][tx * 4];
            float a[4] = {xa.x, xa.y, xa.z, xa.w};
            float w1v[4] = {wb.x, wb.y, wb.z, wb.w};
            float wdv[4] = {wd.x, wd.y, wd.z, wd.w};
#pragma unroll
            for (int i = 0; i < 4; i++)
#pragma unroll
                for (int j = 0; j < 4; j++) {
                    accs[i][j] = fmaf(a[i], w1v[j], accs[i][j]);
                    acct[i][j] = fmaf(a[i], wdv[j], acct[i][j]);
                }
        }
        __syncthreads();
    }

    float ts[4] = {0.f, 0.f, 0.f, 0.f}, ts2[4] = {0.f, 0.f, 0.f, 0.f};
#pragma unroll
    for (int i = 0; i < 4; i++) {
        size_t base = (size_t)(pt0 + ty * 4 + i) * O + o0 + tx * 4;
        float4 sv = {accs[i][0], accs[i][1], accs[i][2], accs[i][3]};
        float4 tv = {acct[i][0], acct[i][1], acct[i][2], acct[i][3]};
        *(float4*)&d_s[base] = sv;
        *(float4*)&d_t[base] = tv;
#pragma unroll
        for (int j = 0; j < 4; j++) {
            ts[j] += acct[i][j];
            ts2[j] = fmaf(acct[i][j], acct[i][j], ts2[j]);
        }
    }
#pragma unroll
    for (int j = 0; j < 4; j++) {
        rts[ty][tx * 4 + j] = ts[j];
        rts2[ty][tx * 4 + j] = ts2[j];
    }
    __syncthreads();
    if (tid < 64) {
        float a = 0.f, a2 = 0.f;
#pragma unroll
        for (int r = 0; r < 16; r++) { a += rts[r][tid]; a2 += rts2[r][tid]; }
        atomicAdd(&d_acc_t[o0 + tid], a);
        atomicAdd(&d_acc_t2[o0 + tid], a2);
    }
}

// gather: thread owns 4 consecutive channels (float4); 64 points per block.
// Stats reduced in smem first -> ONE global atomic per channel per block.
__global__ void gather_kernel(int O) {
    __shared__ float ssum[256 * 4];
    __shared__ float ssq[256 * 4];
    __shared__ float scr[256 * 4];
    int Q = O >> 2;
    int tid = threadIdx.x;
    int q = tid & (Q - 1);
    int sub = tid / Q;
    int nsub = 256 / Q;
    int o = q * 4;
    int pt0 = blockIdx.x * 64;
    float sum[4] = {0,0,0,0}, sq[4] = {0,0,0,0}, cross[4] = {0,0,0,0};
    for (int p = sub; p < 64; p += nsub) {
        int pt = pt0 + p;
        int bb = pt >> 11;
        const int* ip = d_idx + pt * KNN;
        float psum[4] = {0,0,0,0}, psq[4] = {0,0,0,0};
        float pmx[4] = {-FLT_MAX,-FLT_MAX,-FLT_MAX,-FLT_MAX};
        float pmn[4] = {FLT_MAX,FLT_MAX,FLT_MAX,FLT_MAX};
#pragma unroll
        for (int k = 0; k < KNN; k++) {
            int m = ip[k];
            float4 v = *(const float4*)&d_s[(size_t)((bb << 11) + m) * O + o];
            float vv[4] = {v.x, v.y, v.z, v.w};
#pragma unroll
            for (int j = 0; j < 4; j++) {
                psum[j] += vv[j];
                psq[j] = fmaf(vv[j], vv[j], psq[j]);
                pmx[j] = fmaxf(pmx[j], vv[j]);
                pmn[j] = fminf(pmn[j], vv[j]);
            }
        }
        float4 tv = *(const float4*)&d_t[(size_t)pt * O + o];
        float tvv[4] = {tv.x, tv.y, tv.z, tv.w};
#pragma unroll
        for (int j = 0; j < 4; j++) {
            sum[j] += psum[j];
            sq[j] += psq[j];
            cross[j] = fmaf(tvv[j], psum[j], cross[j]);
        }
        float4 mx4 = {pmx[0], pmx[1], pmx[2], pmx[3]};
        float4 mn4 = {pmn[0], pmn[1], pmn[2], pmn[3]};
        *(float4*)&d_maxg[(size_t)pt * O + o] = mx4;
        *(float4*)&d_ming[(size_t)pt * O + o] = mn4;
    }
#pragma unroll
    for (int j = 0; j < 4; j++) {
        ssum[tid * 4 + j] = sum[j];
        ssq[tid * 4 + j] = sq[j];
        scr[tid * 4 + j] = cross[j];
    }
    __syncthreads();
    if (tid < O) {
        int qq = tid >> 2, jj = tid & 3;
        float a = 0.f, a2 = 0.f, a3 = 0.f;
        for (int s = 0; s < nsub; s++) {
            int t = s * Q + qq;
            a += ssum[t * 4 + jj];
            a2 += ssq[t * 4 + jj];
            a3 += scr[t * 4 + jj];
        }
        atomicAdd(&d_acc_s[tid], a);
        atomicAdd(&d_acc_s2[tid], a2);
        atomicAdd(&d_acc_cr[tid], a3);
    }
}

__global__ void bn_kernel(int O, const float* gamma, const float* beta) {
    int o = threadIdx.x;
    if (o >= O) return;
    const float cnt = (float)PTS * (float)KNN;
    float mean = (d_acc_s[o] + (float)KNN * d_acc_t[o]) / cnt;
    float e2 = (d_acc_s2[o] + 2.f * d_acc_cr[o] + (float)KNN * d_acc_t2[o]) / cnt;
    float var = e2 - mean * mean;
    float inv = rsqrtf(var + EPSV);
    float rho = gamma[o] * inv;
    d_rho[o] = rho;
    d_shift[o] = beta[o] - mean * rho;
}

// apply: float4 over channels
__global__ void apply_kernel(int O, int off) {
    int e4 = blockIdx.x * 256 + threadIdx.x;
    int total = PTS * O / 4;
    if (e4 >= total) return;
    int qpr = O >> 2;
    int o = (e4 & (qpr - 1)) * 4;
    int pt = e4 / qpr;
    size_t base = (size_t)pt * O + o;
    float4 r4 = *(const float4*)&d_rho[o];
    float4 sh = *(const float4*)&d_shift[o];
    float4 t4 = *(const float4*)&d_t[base];
    float4 mx = *(const float4*)&d_maxg[base];
    float4 mn = *(const float4*)&d_ming[base];
    float rr[4] = {r4.x, r4.y, r4.z, r4.w};
    float ss[4] = {sh.x, sh.y, sh.z, sh.w};
    float tt[4] = {t4.x, t4.y, t4.z, t4.w};
    float gx[4] = {mx.x, mx.y, mx.z, mx.w};
    float gn[4] = {mn.x, mn.y, mn.z, mn.w};
    float out[4];
#pragma unroll
    for (int j = 0; j < 4; j++) {
        float base_v = tt[j] + (rr[j] >= 0.f ? gx[j] : gn[j]);
        out[j] = fmaxf(fmaf(rr[j], base_v, ss[j]), 0.f);
    }
    float4 o4 = {out[0], out[1], out[2], out[3]};
    *(float4*)&d_feat[(size_t)pt * FEAT + off + o] = o4;
}

__global__ void pool_kernel() {
    int b = blockIdx.x, st = blockIdx.y;
    int c = threadIdx.x;
    float mx = -FLT_MAX, sm = 0.f;
    int n0 = st * 256;
    for (int n = n0; n < n0 + 256; n++) {
        float v = d_feat[(size_t)(b * N + n) * FEAT + c];
        mx = fmaxf(mx, v);
        sm += v;
    }
    d_poolmax[(b * 8 + st) * FEAT + c] = mx;
    d_poolsum[(b * 8 + st) * FEAT + c] = sm;
}

__global__ void head_kernel(const float* fc1_w, const float* fc1_b,
                            const float* ln1_g, const float* ln1_b,
                            const float* fc2_w, const float* fc2_b,
                            const float* ln2_g, const float* ln2_b,
                            float* out) {
    __shared__ float g[1024];
    __shared__ float h[512];
    __shared__ float red[256];
    __shared__ float red2[256];
    int b = blockIdx.x, tid = threadIdx.x;
    for (int c = tid; c < 512; c += 256) {
        float mx = -FLT_MAX, sm = 0.f;
        for (int st = 0; st < 8; st++) {
            mx = fmaxf(mx, d_poolmax[(b * 8 + st) * FEAT + c]);
            sm += d_poolsum[(b * 8 + st) * FEAT + c];
        }
        g[c] = mx;
        g[512 + c] = sm * (1.f / (float)N);
    }
    __syncthreads();
    for (int j = tid; j < 512; j += 256) {
        float acc = fc1_b[j];
        const float* wr = fc1_w + (size_t)j * 1024;
        for (int i = 0; i < 1024; i++) acc = fmaf(g[i], wr[i], acc);
        h[j] = acc;
    }
    __syncthreads();
    {
        float a = h[tid], bb = h[tid + 256];
        red[tid] = a + bb;
        red2[tid] = a * a + bb * bb;
    }
    __syncthreads();
    for (int s = 128; s > 0; s >>= 1) {
        if (tid < s) { red[tid] += red[tid + s]; red2[tid] += red2[tid + s]; }
        __syncthreads();
    }
    float mu = red[0] * (1.f / 512.f);
    float var = red2[0] * (1.f / 512.f) - mu * mu;
    float inv = rsqrtf(var + EPSV);
    __syncthreads();
    for (int j = tid; j < 512; j += 256)
        h[j] = fmaxf(0.f, (h[j] - mu) * inv * ln1_g[j] + ln1_b[j]);
    __syncthreads();
    float z = fc2_b[tid];
    {
        const float* wr = fc2_w + (size_t)tid * 512;
        for (int i = 0; i < 512; i++) z = fmaf(h[i], wr[i], z);
    }
    red[tid] = z;
    red2[tid] = z * z;
    __syncthreads();
    for (int s = 128; s > 0; s >>= 1) {
        if (tid < s) { red[tid] += red[tid + s]; red2[tid] += red2[tid + s]; }
        __syncthreads();
    }
    float mu2 = red[0] * (1.f / 256.f);
    float var2 = red2[0] * (1.f / 256.f) - mu2 * mu2;
    float inv2 = rsqrtf(var2 + EPSV);
    out[b * 256 + tid] = (z - mu2) * inv2 * ln2_g[tid] + ln2_b[tid];
}

// ---------------- launch ----------------

extern "C" void kernel_launch(void* const* d_in, const int* in_sizes, int n_in,
                              void* d_out, int out_size) {
    (void)in_sizes; (void)n_in; (void)out_size;
    const float* points = (const float*)d_in[0];
    const float* Wl[4]  = {(const float*)d_in[1], (const float*)d_in[4],
                           (const float*)d_in[7], (const float*)d_in[10]};
    const float* gl[4]  = {(const float*)d_in[2], (const float*)d_in[5],
                           (const float*)d_in[8], (const float*)d_in[11]};
    const float* bl[4]  = {(const float*)d_in[3], (const float*)d_in[6],
                           (const float*)d_in[9], (const float*)d_in[12]};
    const float* fc1_w = (const float*)d_in[13];
    const float* fc1_b = (const float*)d_in[14];
    const float* ln1_g = (const float*)d_in[15];
    const float* ln1_b = (const float*)d_in[16];
    const float* fc2_w = (const float*)d_in[17];
    const float* fc2_b = (const float*)d_in[18];
    const float* ln2_g = (const float*)d_in[19];
    const float* ln2_b = (const float*)d_in[20];

    const int Cs[4]     = {3, 64, 64, 128};
    const int Os[4]     = {64, 64, 128, 256};
    const int offin[4]  = {0, 0, 64, 128};
    const int offout[4] = {0, 64, 128, 256};
    const int NPAIRS = NB * (NB + 1) / 2;   // 136

    for (int l = 0; l < 4; l++) {
        const float* xin = (l == 0) ? points : nullptr;
        int stride = (l == 0) ? 3 : FEAT;
        int C = Cs[l], O = Os[l];

        xx_kernel<<<(PTS + 255) / 256, 256>>>(xin, stride, offin[l], C);
        dist_kernel<<<dim3(B, NPAIRS), 512>>>(xin, stride, offin[l], C);
        select_kernel<<<PTS / 4, 128>>>();
        st_kernel<<<dim3(PTS / 64, O / 64), 256>>>(xin, stride, offin[l], C, O, Wl[l]);
        gather_kernel<<<PTS / 64, 256>>>(O);
        bn_kernel<<<1, O>>>(O, gl[l], bl[l]);
        apply_kernel<<<(PTS * O / 4 + 255) / 256, 256>>>(O, offout[l]);
    }

    pool_kernel<<<dim3(B, 8), 512>>>();
    head_kernel<<<B, 256>>>(fc1_w, fc1_b, ln1_g, ln1_b,
                            fc2_w, fc2_b, ln2_g, ln2_b, (float*)d_out);
}

// round 16
// speedup vs baseline: 1.6838x; 1.0191x over previous
#include <cuda_runtime.h>
#include <float.h>
#include <math.h>

#define B 8
#define N 2048
#define PTS (B*N)          // 16384
#define KNN 20
#define FEAT 512
#define OMAX 256
#define EPSV 1e-5f
#define NB 16              // N/128 tile count

// ---------------- scratch (static device allocations) ----------------
__device__ float d_dist[(size_t)PTS * N];        // 134 MB
__device__ float d_xx[PTS];
__device__ int   d_idx[PTS * KNN];
__device__ float d_feat[(size_t)PTS * FEAT];
__device__ float d_s[(size_t)PTS * OMAX];
__device__ float d_t[(size_t)PTS * OMAX];
__device__ float d_maxg[(size_t)PTS * OMAX];
__device__ float d_ming[(size_t)PTS * OMAX];
__device__ float d_acc_s[OMAX], d_acc_s2[OMAX], d_acc_cr[OMAX], d_acc_t[OMAX], d_acc_t2[OMAX];
__device__ float d_rho[OMAX], d_shift[OMAX];
__device__ float d_poolmax[B * 8 * FEAT], d_poolsum[B * 8 * FEAT];

// ---------------- kernels ----------------

// squared norms per point; block 0 also zeroes the per-layer accumulators
__global__ void xx_kernel(const float* x, int stride, int off, int C) {
    const float* xp = x ? x : d_feat;
    int p = blockIdx.x * blockDim.x + threadIdx.x;
    if (blockIdx.x == 0) {
        int i = threadIdx.x;
        if (i < OMAX) {
            d_acc_s[i] = 0.f; d_acc_s2[i] = 0.f; d_acc_cr[i] = 0.f;
            d_acc_t[i] = 0.f; d_acc_t2[i] = 0.f;
        }
    }
    if (p >= PTS) return;
    const float* r = xp + (size_t)p * stride + off;
    float s = 0.f;
    for (int c = 0; c < C; c++) { float v = r[c]; s = fmaf(v, v, s); }
    d_xx[p] = s;
}

// layer-1 specialized dist: C=3, all points in smem, direct difference form.
// Block: batch b x 64 rows; thread (r=tid>>2, j=tid&3) covers cols m=16i+4j.
__global__ void __launch_bounds__(256)
dist3_kernel(const float* __restrict__ pts) {
    __shared__ float lin[N * 3];     // 24 KB interleaved x,y,z
    int b = blockIdx.x;
    int n0 = blockIdx.y * 64;
    int tid = threadIdx.x;
    const float* src = pts + (size_t)b * N * 3;
    for (int l = tid; l < N * 3 / 4; l += 256)
        ((float4*)lin)[l] = ((const float4*)src)[l];
    __syncthreads();

    int rl = tid >> 2, j = tid & 3;
    int n = n0 + rl;
    float xn = lin[3 * n], yn = lin[3 * n + 1], zn = lin[3 * n + 2];
    float* orow = d_dist + (size_t)(b * N + n) * N;

#pragma unroll 4
    for (int i = 0; i < 128; i++) {
        int m = 16 * i + 4 * j;
        const float4* p4 = (const float4*)&lin[3 * m];
        float4 f0 = p4[0];   // x0 y0 z0 x1
        float4 f1 = p4[1];   // y1 z1 x2 y2
        float4 f2 = p4[2];   // z2 x3 y3 z3
        float4 o;
        {
            float dx = xn - f0.x, dy = yn - f0.y, dz = zn - f0.z;
            o.x = fmaf(dx, dx, fmaf(dy, dy, dz * dz));
        }
        {
            float dx = xn - f0.w, dy = yn - f1.x, dz = zn - f1.y;
            o.y = fmaf(dx, dx, fmaf(dy, dy, dz * dz));
        }
        {
            float dx = xn - f1.z, dy = yn - f1.w, dz = zn - f2.x;
            o.z = fmaf(dx, dx, fmaf(dy, dy, dz * dz));
        }
        {
            float dx = xn - f2.y, dy = yn - f2.z, dz = zn - f2.w;
            o.w = fmaf(dx, dx, fmaf(dy, dy, dz * dz));
        }
        *(float4*)(orow + m) = o;
    }
}

// dist (general layers): symmetric upper-tri 128x128 block pairs; 512 threads,
// 8x4 micro-tile, register-prefetch double buffering.
__global__ void __launch_bounds__(512, 2)
dist_kernel(const float* __restrict__ x, int stride, int off, int C) {
    const float* xp = x ? x : d_feat;
    int b = blockIdx.x;
    int p = blockIdx.y;
    int pi = 0;
    while (p >= NB - pi) { p -= NB - pi; pi++; }
    int pj = pi + p;
    int n0 = pi * 128, m0 = pj * 128;

    __shared__ float As[16][132];
    __shared__ float Bs[16][132];
    __shared__ float xn_s[128], xm_s[128];

    int tid = threadIdx.x;            // 512 threads
    int tx = tid & 31, ty = tid >> 5;
    if (tid < 128) xn_s[tid] = d_xx[b * N + n0 + tid];
    else if (tid < 256) xm_s[tid - 128] = d_xx[b * N + m0 + tid - 128];

    float acc[8][4];
#pragma unroll
    for (int i = 0; i < 8; i++)
#pragma unroll
        for (int j = 0; j < 4; j++) acc[i][j] = 0.f;

    bool diag = (pi == pj);
    float pa[4], pb[4];
    int lr[4], lc[4];
#pragma unroll
    for (int it = 0; it < 4; it++) {
        int l = tid + it * 512;
        lr[it] = l >> 4;
        lc[it] = l & 15;
    }
#pragma unroll
    for (int it = 0; it < 4; it++) {
        int c = lc[it];
        pa[it] = (c < C) ? xp[(size_t)(b * N + n0 + lr[it]) * stride + off + c] : 0.f;
        pb[it] = (!diag && c < C) ? xp[(size_t)(b * N + m0 + lr[it]) * stride + off + c] : 0.f;
    }

    for (int c0 = 0; c0 < C; c0 += 16) {
#pragma unroll
        for (int it = 0; it < 4; it++) {
            As[lc[it]][lr[it]] = pa[it];
            if (!diag) Bs[lc[it]][lr[it]] = pb[it];
        }
        __syncthreads();
        if (c0 + 16 < C) {
#pragma unroll
            for (int it = 0; it < 4; it++) {
                int c = c0 + 16 + lc[it];
                pa[it] = (c < C) ? xp[(size_t)(b * N + n0 + lr[it]) * stride + off + c] : 0.f;
                pb[it] = (!diag && c < C) ? xp[(size_t)(b * N + m0 + lr[it]) * stride + off + c] : 0.f;
            }
        }
        const float (*Bp)[132] = diag ? As : Bs;
#pragma unroll
        for (int kk = 0; kk < 16; kk++) {
            float4 a0 = *(const float4*)&As[kk][ty * 4];
            float4 a1 = *(const float4*)&As[kk][64 + ty * 4];
            float4 bf = *(const float4*)&Bp[kk][tx * 4];
            float a[8] = {a0.x, a0.y, a0.z, a0.w, a1.x, a1.y, a1.z, a1.w};
            float bb[4] = {bf.x, bf.y, bf.z, bf.w};
#pragma unroll
            for (int i = 0; i < 8; i++)
#pragma unroll
                for (int j = 0; j < 4; j++) acc[i][j] = fmaf(a[i], bb[j], acc[i][j]);
        }
        __syncthreads();
    }

#pragma unroll
    for (int i = 0; i < 8; i++) {
        int nl = (i < 4) ? (ty * 4 + i) : (64 + ty * 4 + i - 4);
        float xn = xn_s[nl];
        float* orow = d_dist + (size_t)(b * N + n0 + nl) * N + m0;
        float4 v;
        v.x = xn + xm_s[tx * 4 + 0] - 2.f * acc[i][0];
        v.y = xn + xm_s[tx * 4 + 1] - 2.f * acc[i][1];
        v.z = xn + xm_s[tx * 4 + 2] - 2.f * acc[i][2];
        v.w = xn + xm_s[tx * 4 + 3] - 2.f * acc[i][3];
        *(float4*)(orow + tx * 4) = v;
    }
    if (!diag) {
#pragma unroll
        for (int j = 0; j < 4; j++) {
            int ml = tx * 4 + j;
            float xm = xm_s[ml];
            float* orow = d_dist + (size_t)(b * N + m0 + ml) * N + n0;
            float4 v0, v1;
            v0.x = xn_s[ty * 4 + 0] + xm - 2.f * acc[0][j];
            v0.y = xn_s[ty * 4 + 1] + xm - 2.f * acc[1][j];
            v0.z = xn_s[ty * 4 + 2] + xm - 2.f * acc[2][j];
            v0.w = xn_s[ty * 4 + 3] + xm - 2.f * acc[3][j];
            v1.x = xn_s[64 + ty * 4 + 0] + xm - 2.f * acc[4][j];
            v1.y = xn_s[64 + ty * 4 + 1] + xm - 2.f * acc[5][j];
            v1.z = xn_s[64 + ty * 4 + 2] + xm - 2.f * acc[6][j];
            v1.w = xn_s[64 + ty * 4 + 3] + xm - 2.f * acc[7][j];
            *(float4*)(orow + ty * 4) = v0;
            *(float4*)(orow + 64 + ty * 4) = v1;
        }
    }
}

// per-row top-KNN: warp per row; value-only fminf reductions + ballot for index.
__global__ void select_kernel() {
    __shared__ float rows[4][64][33];
    int warp = threadIdx.x >> 5, lane = threadIdx.x & 31;
    int pt = blockIdx.x * 4 + warp;
    float (*row)[33] = rows[warp];
    const float4* dr4 = (const float4*)(d_dist + (size_t)pt * N);
#pragma unroll
    for (int it = 0; it < 16; it++) {
        int i4 = lane + 32 * it;
        float4 v = dr4[i4];
        int e = 4 * i4;
        row[e >> 5][e & 31] = v.x;
        row[(e + 1) >> 5][(e + 1) & 31] = v.y;
        row[(e + 2) >> 5][(e + 2) & 31] = v.z;
        row[(e + 3) >> 5][(e + 3) & 31] = v.w;
    }
    __syncwarp();

    float bv = FLT_MAX; int bi = 0;
#pragma unroll 8
    for (int m = 0; m < 64; m++) {
        float v = row[m][lane];
        if (v < bv) { bv = v; bi = lane + 32 * m; }
    }
    int* ip = d_idx + pt * KNN;
    for (int sel = 0; sel < KNN; sel++) {
        float mv = bv;
#pragma unroll
        for (int s = 16; s > 0; s >>= 1)
            mv = fminf(mv, __shfl_xor_sync(0xffffffff, mv, s));
        unsigned mask = __ballot_sync(0xffffffff, bv == mv);
        int ol = __ffs(mask) - 1;                      // owner lane
        int mi = __shfl_sync(0xffffffff, bi, ol);
        if (lane == 0) ip[sel] = mi;
        if (lane == ol) row[mi >> 5][ol] = FLT_MAX;
        __syncwarp();
        float v0 = row[lane][ol];
        float v1 = row[lane + 32][ol];
        float cand = fminf(v0, v1);
        int candi = (v0 <= v1) ? (ol + 32 * lane) : (ol + 32 * (lane + 32));
        float nv = cand;
#pragma unroll
        for (int s = 16; s > 0; s >>= 1)
            nv = fminf(nv, __shfl_xor_sync(0xffffffff, nv, s));
        unsigned m2 = __ballot_sync(0xffffffff, cand == nv);
        int l2 = __ffs(m2) - 1;
        int ni = __shfl_sync(0xffffffff, candi, l2);
        if (lane == ol) { bv = nv; bi = ni; }
        __syncwarp();
    }
}

// st: register-tiled dual GEMM. Block = 64 points x 64 outs, 4x4 per thread.
// Stats reduced in smem first -> ONE global atomic per channel per block.
__global__ void st_kernel(const float* __restrict__ x, int stride, int off, int C,
                          int O, const float* __restrict__ W) {
    const float* xp = x ? x : d_feat;
    int pt0 = blockIdx.x * 64;
    int o0 = blockIdx.y * 64;
    __shared__ float xs[16][68];
    __shared__ float w1s[16][68];
    __shared__ float wds[16][68];
    __shared__ float rts[16][64];
    __shared__ float rts2[16][64];
    int tid = threadIdx.x;
    int tx = tid & 15, ty = tid >> 4;
    float accs[4][4], acct[4][4];
#pragma unroll
    for (int i = 0; i < 4; i++)
#pragma unroll
        for (int j = 0; j < 4; j++) { accs[i][j] = 0.f; acct[i][j] = 0.f; }

    for (int c0 = 0; c0 < C; c0 += 16) {
        for (int l = tid; l < 1024; l += 256) {
            int r = l >> 4, cc = l & 15;
            int c = c0 + cc;
            xs[cc][r] = (c < C) ? xp[(size_t)(pt0 + r) * stride + off + c] : 0.f;
            float a = 0.f, d = 0.f;
            if (c < C) {
                a = W[(size_t)(o0 + r) * 2 * C + c];
                d = W[(size_t)(o0 + r) * 2 * C + C + c] - a;
            }
            w1s[cc][r] = a;
            wds[cc][r] = d;
        }
        __syncthreads();
#pragma unroll
        for (int kk = 0; kk < 16; kk++) {
            float4 xa = *(const float4*)&xs[kk][ty * 4];
            float4 wb = *(const float4*)&w1s[kk][tx * 4];
            float4 wd = *(const float4*)&wds[kk][tx * 4];
            float a[4] = {xa.x, xa.y, xa.z, xa.w};
            float w1v[4] = {wb.x, wb.y, wb.z, wb.w};
            float wdv[4] = {wd.x, wd.y, wd.z, wd.w};
#pragma unroll
            for (int i = 0; i < 4; i++)
#pragma unroll
                for (int j = 0; j < 4; j++) {
                    accs[i][j] = fmaf(a[i], w1v[j], accs[i][j]);
                    acct[i][j] = fmaf(a[i], wdv[j], acct[i][j]);
                }
        }
        __syncthreads();
    }

    float ts[4] = {0.f, 0.f, 0.f, 0.f}, ts2[4] = {0.f, 0.f, 0.f, 0.f};
#pragma unroll
    for (int i = 0; i < 4; i++) {
        size_t base = (size_t)(pt0 + ty * 4 + i) * O + o0 + tx * 4;
        float4 sv = {accs[i][0], accs[i][1], accs[i][2], accs[i][3]};
        float4 tv = {acct[i][0], acct[i][1], acct[i][2], acct[i][3]};
        *(float4*)&d_s[base] = sv;
        *(float4*)&d_t[base] = tv;
#pragma unroll
        for (int j = 0; j < 4; j++) {
            ts[j] += acct[i][j];
            ts2[j] = fmaf(acct[i][j], acct[i][j], ts2[j]);
        }
    }
#pragma unroll
    for (int j = 0; j < 4; j++) {
        rts[ty][tx * 4 + j] = ts[j];
        rts2[ty][tx * 4 + j] = ts2[j];
    }
    __syncthreads();
    if (tid < 64) {
        float a = 0.f, a2 = 0.f;
#pragma unroll
        for (int r = 0; r < 16; r++) { a += rts[r][tid]; a2 += rts2[r][tid]; }
        atomicAdd(&d_acc_t[o0 + tid], a);
        atomicAdd(&d_acc_t2[o0 + tid], a2);
    }
}

// gather: thread owns 4 consecutive channels (float4); 64 points per block.
// Stats reduced in smem first -> ONE global atomic per channel per block.
__global__ void gather_kernel(int O) {
    __shared__ float ssum[256 * 4];
    __shared__ float ssq[256 * 4];
    __shared__ float scr[256 * 4];
    int Q = O >> 2;
    int tid = threadIdx.x;
    int q = tid & (Q - 1);
    int sub = tid / Q;
    int nsub = 256 / Q;
    int o = q * 4;
    int pt0 = blockIdx.x * 64;
    float sum[4] = {0,0,0,0}, sq[4] = {0,0,0,0}, cross[4] = {0,0,0,0};
    for (int p = sub; p < 64; p += nsub) {
        int pt = pt0 + p;
        int bb = pt >> 11;
        const int* ip = d_idx + pt * KNN;
        float psum[4] = {0,0,0,0}, psq[4] = {0,0,0,0};
        float pmx[4] = {-FLT_MAX,-FLT_MAX,-FLT_MAX,-FLT_MAX};
        float pmn[4] = {FLT_MAX,FLT_MAX,FLT_MAX,FLT_MAX};
#pragma unroll
        for (int k = 0; k < KNN; k++) {
            int m = ip[k];
            float4 v = *(const float4*)&d_s[(size_t)((bb << 11) + m) * O + o];
            float vv[4] = {v.x, v.y, v.z, v.w};
#pragma unroll
            for (int j = 0; j < 4; j++) {
                psum[j] += vv[j];
                psq[j] = fmaf(vv[j], vv[j], psq[j]);
                pmx[j] = fmaxf(pmx[j], vv[j]);
                pmn[j] = fminf(pmn[j], vv[j]);
            }
        }
        float4 tv = *(const float4*)&d_t[(size_t)pt * O + o];
        float tvv[4] = {tv.x, tv.y, tv.z, tv.w};
#pragma unroll
        for (int j = 0; j < 4; j++) {
            sum[j] += psum[j];
            sq[j] += psq[j];
            cross[j] = fmaf(tvv[j], psum[j], cross[j]);
        }
        float4 mx4 = {pmx[0], pmx[1], pmx[2], pmx[3]};
        float4 mn4 = {pmn[0], pmn[1], pmn[2], pmn[3]};
        *(float4*)&d_maxg[(size_t)pt * O + o] = mx4;
        *(float4*)&d_ming[(size_t)pt * O + o] = mn4;
    }
#pragma unroll
    for (int j = 0; j < 4; j++) {
        ssum[tid * 4 + j] = sum[j];
        ssq[tid * 4 + j] = sq[j];
        scr[tid * 4 + j] = cross[j];
    }
    __syncthreads();
    if (tid < O) {
        int qq = tid >> 2, jj = tid & 3;
        float a = 0.f, a2 = 0.f, a3 = 0.f;
        for (int s = 0; s < nsub; s++) {
            int t = s * Q + qq;
            a += ssum[t * 4 + jj];
            a2 += ssq[t * 4 + jj];
            a3 += scr[t * 4 + jj];
        }
        atomicAdd(&d_acc_s[tid], a);
        atomicAdd(&d_acc_s2[tid], a2);
        atomicAdd(&d_acc_cr[tid], a3);
    }
}

__global__ void bn_kernel(int O, const float* gamma, const float* beta) {
    int o = threadIdx.x;
    if (o >= O) return;
    const float cnt = (float)PTS * (float)KNN;
    float mean = (d_acc_s[o] + (float)KNN * d_acc_t[o]) / cnt;
    float e2 = (d_acc_s2[o] + 2.f * d_acc_cr[o] + (float)KNN * d_acc_t2[o]) / cnt;
    float var = e2 - mean * mean;
    float inv = rsqrtf(var + EPSV);
    float rho = gamma[o] * inv;
    d_rho[o] = rho;
    d_shift[o] = beta[o] - mean * rho;
}

// apply: float4 over channels
__global__ void apply_kernel(int O, int off) {
    int e4 = blockIdx.x * 256 + threadIdx.x;
    int total = PTS * O / 4;
    if (e4 >= total) return;
    int qpr = O >> 2;
    int o = (e4 & (qpr - 1)) * 4;
    int pt = e4 / qpr;
    size_t base = (size_t)pt * O + o;
    float4 r4 = *(const float4*)&d_rho[o];
    float4 sh = *(const float4*)&d_shift[o];
    float4 t4 = *(const float4*)&d_t[base];
    float4 mx = *(const float4*)&d_maxg[base];
    float4 mn = *(const float4*)&d_ming[base];
    float rr[4] = {r4.x, r4.y, r4.z, r4.w};
    float ss[4] = {sh.x, sh.y, sh.z, sh.w};
    float tt[4] = {t4.x, t4.y, t4.z, t4.w};
    float gx[4] = {mx.x, mx.y, mx.z, mx.w};
    float gn[4] = {mn.x, mn.y, mn.z, mn.w};
    float out[4];
#pragma unroll
    for (int j = 0; j < 4; j++) {
        float base_v = tt[j] + (rr[j] >= 0.f ? gx[j] : gn[j]);
        out[j] = fmaxf(fmaf(rr[j], base_v, ss[j]), 0.f);
    }
    float4 o4 = {out[0], out[1], out[2], out[3]};
    *(float4*)&d_feat[(size_t)pt * FEAT + off + o] = o4;
}

__global__ void pool_kernel() {
    int b = blockIdx.x, st = blockIdx.y;
    int c = threadIdx.x;
    float mx = -FLT_MAX, sm = 0.f;
    int n0 = st * 256;
    for (int n = n0; n < n0 + 256; n++) {
        float v = d_feat[(size_t)(b * N + n) * FEAT + c];
        mx = fmaxf(mx, v);
        sm += v;
    }
    d_poolmax[(b * 8 + st) * FEAT + c] = mx;
    d_poolsum[(b * 8 + st) * FEAT + c] = sm;
}

__global__ void head_kernel(const float* fc1_w, const float* fc1_b,
                            const float* ln1_g, const float* ln1_b,
                            const float* fc2_w, const float* fc2_b,
                            const float* ln2_g, const float* ln2_b,
                            float* out) {
    __shared__ float g[1024];
    __shared__ float h[512];
    __shared__ float red[256];
    __shared__ float red2[256];
    int b = blockIdx.x, tid = threadIdx.x;
    for (int c = tid; c < 512; c += 256) {
        float mx = -FLT_MAX, sm = 0.f;
        for (int st = 0; st < 8; st++) {
            mx = fmaxf(mx, d_poolmax[(b * 8 + st) * FEAT + c]);
            sm += d_poolsum[(b * 8 + st) * FEAT + c];
        }
        g[c] = mx;
        g[512 + c] = sm * (1.f / (float)N);
    }
    __syncthreads();
    for (int j = tid; j < 512; j += 256) {
        float acc = fc1_b[j];
        const float* wr = fc1_w + (size_t)j * 1024;
        for (int i = 0; i < 1024; i++) acc = fmaf(g[i], wr[i], acc);
        h[j] = acc;
    }
    __syncthreads();
    {
        float a = h[tid], bb = h[tid + 256];
        red[tid] = a + bb;
        red2[tid] = a * a + bb * bb;
    }
    __syncthreads();
    for (int s = 128; s > 0; s >>= 1) {
        if (tid < s) { red[tid] += red[tid + s]; red2[tid] += red2[tid + s]; }
        __syncthreads();
    }
    float mu = red[0] * (1.f / 512.f);
    float var = red2[0] * (1.f / 512.f) - mu * mu;
    float inv = rsqrtf(var + EPSV);
    __syncthreads();
    for (int j = tid; j < 512; j += 256)
        h[j] = fmaxf(0.f, (h[j] - mu) * inv * ln1_g[j] + ln1_b[j]);
    __syncthreads();
    float z = fc2_b[tid];
    {
        const float* wr = fc2_w + (size_t)tid * 512;
        for (int i = 0; i < 512; i++) z = fmaf(h[i], wr[i], z);
    }
    red[tid] = z;
    red2[tid] = z * z;
    __syncthreads();
    for (int s = 128; s > 0; s >>= 1) {
        if (tid < s) { red[tid] += red[tid + s]; red2[tid] += red2[tid + s]; }
        __syncthreads();
    }
    float mu2 = red[0] * (1.f / 256.f);
    float var2 = red2[0] * (1.f / 256.f) - mu2 * mu2;
    float inv2 = rsqrtf(var2 + EPSV);
    out[b * 256 + tid] = (z - mu2) * inv2 * ln2_g[tid] + ln2_b[tid];
}

// ---------------- launch ----------------

extern "C" void kernel_launch(void* const* d_in, const int* in_sizes, int n_in,
                              void* d_out, int out_size) {
    (void)in_sizes; (void)n_in; (void)out_size;
    const float* points = (const float*)d_in[0];
    const float* Wl[4]  = {(const float*)d_in[1], (const float*)d_in[4],
                           (const float*)d_in[7], (const float*)d_in[10]};
    const float* gl[4]  = {(const float*)d_in[2], (const float*)d_in[5],
                           (const float*)d_in[8], (const float*)d_in[11]};
    const float* bl[4]  = {(const float*)d_in[3], (const float*)d_in[6],
                           (const float*)d_in[9], (const float*)d_in[12]};
    const float* fc1_w = (const float*)d_in[13];
    const float* fc1_b = (const float*)d_in[14];
    const float* ln1_g = (const float*)d_in[15];
    const float* ln1_b = (const float*)d_in[16];
    const float* fc2_w = (const float*)d_in[17];
    const float* fc2_b = (const float*)d_in[18];
    const float* ln2_g = (const float*)d_in[19];
    const float* ln2_b = (const float*)d_in[20];

    const int Cs[4]     = {3, 64, 64, 128};
    const int Os[4]     = {64, 64, 128, 256};
    const int offin[4]  = {0, 0, 64, 128};
    const int offout[4] = {0, 64, 128, 256};
    const int NPAIRS = NB * (NB + 1) / 2;   // 136

    for (int l = 0; l < 4; l++) {
        const float* xin = (l == 0) ? points : nullptr;
        int stride = (l == 0) ? 3 : FEAT;
        int C = Cs[l], O = Os[l];

        xx_kernel<<<(PTS + 255) / 256, 256>>>(xin, stride, offin[l], C);
        if (l == 0)
            dist3_kernel<<<dim3(B, N / 64), 256>>>(points);
        else
            dist_kernel<<<dim3(B, NPAIRS), 512>>>(xin, stride, offin[l], C);
        select_kernel<<<PTS / 4, 128>>>();
        st_kernel<<<dim3(PTS / 64, O / 64), 256>>>(xin, stride, offin[l], C, O, Wl[l]);
        gather_kernel<<<PTS / 64, 256>>>(O);
        bn_kernel<<<1, O>>>(O, gl[l], bl[l]);
        apply_kernel<<<(PTS * O / 4 + 255) / 256, 256>>>(O, offout[l]);
    }

    pool_kernel<<<dim3(B, 8), 512>>>();
    head_kernel<<<B, 256>>>(fc1_w, fc1_b, ln1_g, ln1_b,
                            fc2_w, fc2_b, ln2_g, ln2_b, (float*)d_out);
}

// round 17
// speedup vs baseline: 1.7721x; 1.0524x over previous
#include <cuda_runtime.h>
#include <float.h>
#include <math.h>

#define B 8
#define N 2048
#define PTS (B*N)          // 16384
#define KNN 20
#define FEAT 512
#define OMAX 256
#define EPSV 1e-5f
#define NB 16              // N/128 tile count

// ---------------- scratch (static device allocations) ----------------
__device__ float d_dist[(size_t)PTS * N];        // 134 MB
__device__ float d_xx[PTS];
__device__ int   d_idx[PTS * KNN];
__device__ float d_feat[(size_t)PTS * FEAT];
__device__ float d_s[(size_t)PTS * OMAX];
__device__ float d_t[(size_t)PTS * OMAX];
__device__ float d_maxg[(size_t)PTS * OMAX];
__device__ float d_ming[(size_t)PTS * OMAX];
__device__ float d_acc_s[OMAX], d_acc_s2[OMAX], d_acc_cr[OMAX], d_acc_t[OMAX], d_acc_t2[OMAX];
__device__ float d_rho[OMAX], d_shift[OMAX];
__device__ float d_poolmax[B * 8 * FEAT], d_poolsum[B * 8 * FEAT];

// monotone unsigned key: preserves float order exactly
__device__ __forceinline__ unsigned fkey(float v) {
    unsigned u = __float_as_uint(v);
    return (u & 0x80000000u) ? ~u : (u | 0x80000000u);
}

// ---------------- kernels ----------------

__global__ void zero_acc_kernel() {
    int i = threadIdx.x;
    if (i < OMAX) {
        d_acc_s[i] = 0.f; d_acc_s2[i] = 0.f; d_acc_cr[i] = 0.f;
        d_acc_t[i] = 0.f; d_acc_t2[i] = 0.f;
    }
}

// squared norms per point; block 0 also zeroes the per-layer accumulators
__global__ void xx_kernel(const float* x, int stride, int off, int C) {
    const float* xp = x ? x : d_feat;
    int p = blockIdx.x * blockDim.x + threadIdx.x;
    if (blockIdx.x == 0) {
        int i = threadIdx.x;
        if (i < OMAX) {
            d_acc_s[i] = 0.f; d_acc_s2[i] = 0.f; d_acc_cr[i] = 0.f;
            d_acc_t[i] = 0.f; d_acc_t2[i] = 0.f;
        }
    }
    if (p >= PTS) return;
    const float* r = xp + (size_t)p * stride + off;
    float s = 0.f;
    for (int c = 0; c < C; c++) { float v = r[c]; s = fmaf(v, v, s); }
    d_xx[p] = s;
}

// layer-1 specialized dist: C=3, all points in smem, direct difference form.
__global__ void __launch_bounds__(256)
dist3_kernel(const float* __restrict__ pts) {
    __shared__ float lin[N * 3];     // 24 KB interleaved x,y,z
    int b = blockIdx.x;
    int n0 = blockIdx.y * 64;
    int tid = threadIdx.x;
    const float* src = pts + (size_t)b * N * 3;
    for (int l = tid; l < N * 3 / 4; l += 256)
        ((float4*)lin)[l] = ((const float4*)src)[l];
    __syncthreads();

    int rl = tid >> 2, j = tid & 3;
    int n = n0 + rl;
    float xn = lin[3 * n], yn = lin[3 * n + 1], zn = lin[3 * n + 2];
    float* orow = d_dist + (size_t)(b * N + n) * N;

#pragma unroll 4
    for (int i = 0; i < 128; i++) {
        int m = 16 * i + 4 * j;
        const float4* p4 = (const float4*)&lin[3 * m];
        float4 f0 = p4[0];
        float4 f1 = p4[1];
        float4 f2 = p4[2];
        float4 o;
        {
            float dx = xn - f0.x, dy = yn - f0.y, dz = zn - f0.z;
            o.x = fmaf(dx, dx, fmaf(dy, dy, dz * dz));
        }
        {
            float dx = xn - f0.w, dy = yn - f1.x, dz = zn - f1.y;
            o.y = fmaf(dx, dx, fmaf(dy, dy, dz * dz));
        }
        {
            float dx = xn - f1.z, dy = yn - f1.w, dz = zn - f2.x;
            o.z = fmaf(dx, dx, fmaf(dy, dy, dz * dz));
        }
        {
            float dx = xn - f2.y, dy = yn - f2.z, dz = zn - f2.w;
            o.w = fmaf(dx, dx, fmaf(dy, dy, dz * dz));
        }
        *(float4*)(orow + m) = o;
    }
}

// dist (general layers): symmetric upper-tri 128x128 block pairs; 512 threads,
// 8x4 micro-tile, register-prefetch double buffering.
__global__ void __launch_bounds__(512, 2)
dist_kernel(const float* __restrict__ x, int stride, int off, int C) {
    const float* xp = x ? x : d_feat;
    int b = blockIdx.x;
    int p = blockIdx.y;
    int pi = 0;
    while (p >= NB - pi) { p -= NB - pi; pi++; }
    int pj = pi + p;
    int n0 = pi * 128, m0 = pj * 128;

    __shared__ float As[16][132];
    __shared__ float Bs[16][132];
    __shared__ float xn_s[128], xm_s[128];

    int tid = threadIdx.x;
    int tx = tid & 31, ty = tid >> 5;
    if (tid < 128) xn_s[tid] = d_xx[b * N + n0 + tid];
    else if (tid < 256) xm_s[tid - 128] = d_xx[b * N + m0 + tid - 128];

    float acc[8][4];
#pragma unroll
    for (int i = 0; i < 8; i++)
#pragma unroll
        for (int j = 0; j < 4; j++) acc[i][j] = 0.f;

    bool diag = (pi == pj);
    float pa[4], pb[4];
    int lr[4], lc[4];
#pragma unroll
    for (int it = 0; it < 4; it++) {
        int l = tid + it * 512;
        lr[it] = l >> 4;
        lc[it] = l & 15;
    }
#pragma unroll
    for (int it = 0; it < 4; it++) {
        int c = lc[it];
        pa[it] = (c < C) ? xp[(size_t)(b * N + n0 + lr[it]) * stride + off + c] : 0.f;
        pb[it] = (!diag && c < C) ? xp[(size_t)(b * N + m0 + lr[it]) * stride + off + c] : 0.f;
    }

    for (int c0 = 0; c0 < C; c0 += 16) {
#pragma unroll
        for (int it = 0; it < 4; it++) {
            As[lc[it]][lr[it]] = pa[it];
            if (!diag) Bs[lc[it]][lr[it]] = pb[it];
        }
        __syncthreads();
        if (c0 + 16 < C) {
#pragma unroll
            for (int it = 0; it < 4; it++) {
                int c = c0 + 16 + lc[it];
                pa[it] = (c < C) ? xp[(size_t)(b * N + n0 + lr[it]) * stride + off + c] : 0.f;
                pb[it] = (!diag && c < C) ? xp[(size_t)(b * N + m0 + lr[it]) * stride + off + c] : 0.f;
            }
        }
        const float (*Bp)[132] = diag ? As : Bs;
#pragma unroll
        for (int kk = 0; kk < 16; kk++) {
            float4 a0 = *(const float4*)&As[kk][ty * 4];
            float4 a1 = *(const float4*)&As[kk][64 + ty * 4];
            float4 bf = *(const float4*)&Bp[kk][tx * 4];
            float a[8] = {a0.x, a0.y, a0.z, a0.w, a1.x, a1.y, a1.z, a1.w};
            float bb[4] = {bf.x, bf.y, bf.z, bf.w};
#pragma unroll
            for (int i = 0; i < 8; i++)
#pragma unroll
                for (int j = 0; j < 4; j++) acc[i][j] = fmaf(a[i], bb[j], acc[i][j]);
        }
        __syncthreads();
    }

#pragma unroll
    for (int i = 0; i < 8; i++) {
        int nl = (i < 4) ? (ty * 4 + i) : (64 + ty * 4 + i - 4);
        float xn = xn_s[nl];
        float* orow = d_dist + (size_t)(b * N + n0 + nl) * N + m0;
        float4 v;
        v.x = xn + xm_s[tx * 4 + 0] - 2.f * acc[i][0];
        v.y = xn + xm_s[tx * 4 + 1] - 2.f * acc[i][1];
        v.z = xn + xm_s[tx * 4 + 2] - 2.f * acc[i][2];
        v.w = xn + xm_s[tx * 4 + 3] - 2.f * acc[i][3];
        *(float4*)(orow + tx * 4) = v;
    }
    if (!diag) {
#pragma unroll
        for (int j = 0; j < 4; j++) {
            int ml = tx * 4 + j;
            float xm = xm_s[ml];
            float* orow = d_dist + (size_t)(b * N + m0 + ml) * N + n0;
            float4 v0, v1;
            v0.x = xn_s[ty * 4 + 0] + xm - 2.f * acc[0][j];
            v0.y = xn_s[ty * 4 + 1] + xm - 2.f * acc[1][j];
            v0.z = xn_s[ty * 4 + 2] + xm - 2.f * acc[2][j];
            v0.w = xn_s[ty * 4 + 3] + xm - 2.f * acc[3][j];
            v1.x = xn_s[64 + ty * 4 + 0] + xm - 2.f * acc[4][j];
            v1.y = xn_s[64 + ty * 4 + 1] + xm - 2.f * acc[5][j];
            v1.z = xn_s[64 + ty * 4 + 2] + xm - 2.f * acc[6][j];
            v1.w = xn_s[64 + ty * 4 + 3] + xm - 2.f * acc[7][j];
            *(float4*)(orow + ty * 4) = v0;
            *(float4*)(orow + 64 + ty * 4) = v1;
        }
    }
}

// per-row top-KNN: warp per row; rows stored as monotone unsigned keys so
// warp mins use single-instruction __reduce_min_sync; exact float ordering.
__global__ void select_kernel() {
    __shared__ unsigned rows[4][64][33];
    int warp = threadIdx.x >> 5, lane = threadIdx.x & 31;
    int pt = blockIdx.x * 4 + warp;
    unsigned (*row)[33] = rows[warp];
    const float4* dr4 = (const float4*)(d_dist + (size_t)pt * N);
#pragma unroll
    for (int it = 0; it < 16; it++) {
        int i4 = lane + 32 * it;
        float4 v = dr4[i4];
        int e = 4 * i4;
        row[e >> 5][e & 31] = fkey(v.x);
        row[(e + 1) >> 5][(e + 1) & 31] = fkey(v.y);
        row[(e + 2) >> 5][(e + 2) & 31] = fkey(v.z);
        row[(e + 3) >> 5][(e + 3) & 31] = fkey(v.w);
    }
    __syncwarp();

    unsigned bv = 0xffffffffu; int bi = 0;
#pragma unroll 8
    for (int m = 0; m < 64; m++) {
        unsigned v = row[m][lane];
        if (v < bv) { bv = v; bi = lane + 32 * m; }
    }
    int* ip = d_idx + pt * KNN;
    for (int sel = 0; sel < KNN; sel++) {
        unsigned mv = __reduce_min_sync(0xffffffffu, bv);
        unsigned mask = __ballot_sync(0xffffffffu, bv == mv);
        int ol = __ffs(mask) - 1;                      // owner lane
        int mi = __shfl_sync(0xffffffffu, bi, ol);
        if (lane == 0) ip[sel] = mi;
        if (lane == ol) row[mi >> 5][ol] = 0xffffffffu;
        __syncwarp();
        // cooperative rescan of owner strip (elements ol + 32*m)
        unsigned v0 = row[lane][ol];
        unsigned v1 = row[lane + 32][ol];
        unsigned cand = (v0 <= v1) ? v0 : v1;
        int candi = (v0 <= v1) ? (ol + 32 * lane) : (ol + 32 * (lane + 32));
        unsigned nv = __reduce_min_sync(0xffffffffu, cand);
        unsigned m2 = __ballot_sync(0xffffffffu, cand == nv);
        int l2 = __ffs(m2) - 1;
        int ni = __shfl_sync(0xffffffffu, candi, l2);
        if (lane == ol) { bv = nv; bi = ni; }
        __syncwarp();
    }
}

// st: register-tiled dual GEMM. Block = 64 points x 64 outs, 4x4 per thread.
// Stats reduced in smem first -> ONE global atomic per channel per block.
__global__ void st_kernel(const float* __restrict__ x, int stride, int off, int C,
                          int O, const float* __restrict__ W) {
    const float* xp = x ? x : d_feat;
    int pt0 = blockIdx.x * 64;
    int o0 = blockIdx.y * 64;
    __shared__ float xs[16][68];
    __shared__ float w1s[16][68];
    __shared__ float wds[16][68];
    __shared__ float rts[16][64];
    __shared__ float rts2[16][64];
    int tid = threadIdx.x;
    int tx = tid & 15, ty = tid >> 4;
    float accs[4][4], acct[4][4];
#pragma unroll
    for (int i = 0; i < 4; i++)
#pragma unroll
        for (int j = 0; j < 4; j++) { accs[i][j] = 0.f; acct[i][j] = 0.f; }

    for (int c0 = 0; c0 < C; c0 += 16) {
        for (int l = tid; l < 1024; l += 256) {
            int r = l >> 4, cc = l & 15;
            int c = c0 + cc;
            xs[cc][r] = (c < C) ? xp[(size_t)(pt0 + r) * stride + off + c] : 0.f;
            float a = 0.f, d = 0.f;
            if (c < C) {
                a = W[(size_t)(o0 + r) * 2 * C + c];
                d = W[(size_t)(o0 + r) * 2 * C + C + c] - a;
            }
            w1s[cc][r] = a;
            wds[cc][r] = d;
        }
        __syncthreads();
#pragma unroll
        for (int kk = 0; kk < 16; kk++) {
            float4 xa = *(const float4*)&xs[kk][ty * 4];
            float4 wb = *(const float4*)&w1s[kk][tx * 4];
            float4 wd = *(const float4*)&wds[kk][tx * 4];
            float a[4] = {xa.x, xa.y, xa.z, xa.w};
            float w1v[4] = {wb.x, wb.y, wb.z, wb.w};
            float wdv[4] = {wd.x, wd.y, wd.z, wd.w};
#pragma unroll
            for (int i = 0; i < 4; i++)
#pragma unroll
                for (int j = 0; j < 4; j++) {
                    accs[i][j] = fmaf(a[i], w1v[j], accs[i][j]);
                    acct[i][j] = fmaf(a[i], wdv[j], acct[i][j]);
                }
        }
        __syncthreads();
    }

    float ts[4] = {0.f, 0.f, 0.f, 0.f}, ts2[4] = {0.f, 0.f, 0.f, 0.f};
#pragma unroll
    for (int i = 0; i < 4; i++) {
        size_t base = (size_t)(pt0 + ty * 4 + i) * O + o0 + tx * 4;
        float4 sv = {accs[i][0], accs[i][1], accs[i][2], accs[i][3]};
        float4 tv = {acct[i][0], acct[i][1], acct[i][2], acct[i][3]};
        *(float4*)&d_s[base] = sv;
        *(float4*)&d_t[base] = tv;
#pragma unroll
        for (int j = 0; j < 4; j++) {
            ts[j] += acct[i][j];
            ts2[j] = fmaf(acct[i][j], acct[i][j], ts2[j]);
        }
    }
#pragma unroll
    for (int j = 0; j < 4; j++) {
        rts[ty][tx * 4 + j] = ts[j];
        rts2[ty][tx * 4 + j] = ts2[j];
    }
    __syncthreads();
    if (tid < 64) {
        float a = 0.f, a2 = 0.f;
#pragma unroll
        for (int r = 0; r < 16; r++) { a += rts[r][tid]; a2 += rts2[r][tid]; }
        atomicAdd(&d_acc_t[o0 + tid], a);
        atomicAdd(&d_acc_t2[o0 + tid], a2);
    }
}

// gather: thread owns 4 consecutive channels (float4); 64 points per block.
// Stats reduced in smem first -> ONE global atomic per channel per block.
__global__ void gather_kernel(int O) {
    __shared__ float ssum[256 * 4];
    __shared__ float ssq[256 * 4];
    __shared__ float scr[256 * 4];
    int Q = O >> 2;
    int tid = threadIdx.x;
    int q = tid & (Q - 1);
    int sub = tid / Q;
    int nsub = 256 / Q;
    int o = q * 4;
    int pt0 = blockIdx.x * 64;
    float sum[4] = {0,0,0,0}, sq[4] = {0,0,0,0}, cross[4] = {0,0,0,0};
    for (int p = sub; p < 64; p += nsub) {
        int pt = pt0 + p;
        int bb = pt >> 11;
        const int* ip = d_idx + pt * KNN;
        float psum[4] = {0,0,0,0}, psq[4] = {0,0,0,0};
        float pmx[4] = {-FLT_MAX,-FLT_MAX,-FLT_MAX,-FLT_MAX};
        float pmn[4] = {FLT_MAX,FLT_MAX,FLT_MAX,FLT_MAX};
#pragma unroll
        for (int k = 0; k < KNN; k++) {
            int m = ip[k];
            float4 v = *(const float4*)&d_s[(size_t)((bb << 11) + m) * O + o];
            float vv[4] = {v.x, v.y, v.z, v.w};
#pragma unroll
            for (int j = 0; j < 4; j++) {
                psum[j] += vv[j];
                psq[j] = fmaf(vv[j], vv[j], psq[j]);
                pmx[j] = fmaxf(pmx[j], vv[j]);
                pmn[j] = fminf(pmn[j], vv[j]);
            }
        }
        float4 tv = *(const float4*)&d_t[(size_t)pt * O + o];
        float tvv[4] = {tv.x, tv.y, tv.z, tv.w};
#pragma unroll
        for (int j = 0; j < 4; j++) {
            sum[j] += psum[j];
            sq[j] += psq[j];
            cross[j] = fmaf(tvv[j], psum[j], cross[j]);
        }
        float4 mx4 = {pmx[0], pmx[1], pmx[2], pmx[3]};
        float4 mn4 = {pmn[0], pmn[1], pmn[2], pmn[3]};
        *(float4*)&d_maxg[(size_t)pt * O + o] = mx4;
        *(float4*)&d_ming[(size_t)pt * O + o] = mn4;
    }
#pragma unroll
    for (int j = 0; j < 4; j++) {
        ssum[tid * 4 + j] = sum[j];
        ssq[tid * 4 + j] = sq[j];
        scr[tid * 4 + j] = cross[j];
    }
    __syncthreads();
    if (tid < O) {
        int qq = tid >> 2, jj = tid & 3;
        float a = 0.f, a2 = 0.f, a3 = 0.f;
        for (int s = 0; s < nsub; s++) {
            int t = s * Q + qq;
            a += ssum[t * 4 + jj];
            a2 += ssq[t * 4 + jj];
            a3 += scr[t * 4 + jj];
        }
        atomicAdd(&d_acc_s[tid], a);
        atomicAdd(&d_acc_s2[tid], a2);
        atomicAdd(&d_acc_cr[tid], a3);
    }
}

__global__ void bn_kernel(int O, const float* gamma, const float* beta) {
    int o = threadIdx.x;
    if (o >= O) return;
    const float cnt = (float)PTS * (float)KNN;
    float mean = (d_acc_s[o] + (float)KNN * d_acc_t[o]) / cnt;
    float e2 = (d_acc_s2[o] + 2.f * d_acc_cr[o] + (float)KNN * d_acc_t2[o]) / cnt;
    float var = e2 - mean * mean;
    float inv = rsqrtf(var + EPSV);
    float rho = gamma[o] * inv;
    d_rho[o] = rho;
    d_shift[o] = beta[o] - mean * rho;
}

// apply: float4 over channels
__global__ void apply_kernel(int O, int off) {
    int e4 = blockIdx.x * 256 + threadIdx.x;
    int total = PTS * O / 4;
    if (e4 >= total) return;
    int qpr = O >> 2;
    int o = (e4 & (qpr - 1)) * 4;
    int pt = e4 / qpr;
    size_t base = (size_t)pt * O + o;
    float4 r4 = *(const float4*)&d_rho[o];
    float4 sh = *(const float4*)&d_shift[o];
    float4 t4 = *(const float4*)&d_t[base];
    float4 mx = *(const float4*)&d_maxg[base];
    float4 mn = *(const float4*)&d_ming[base];
    float rr[4] = {r4.x, r4.y, r4.z, r4.w};
    float ss[4] = {sh.x, sh.y, sh.z, sh.w};
    float tt[4] = {t4.x, t4.y, t4.z, t4.w};
    float gx[4] = {mx.x, mx.y, mx.z, mx.w};
    float gn[4] = {mn.x, mn.y, mn.z, mn.w};
    float out[4];
#pragma unroll
    for (int j = 0; j < 4; j++) {
        float base_v = tt[j] + (rr[j] >= 0.f ? gx[j] : gn[j]);
        out[j] = fmaxf(fmaf(rr[j], base_v, ss[j]), 0.f);
    }
    float4 o4 = {out[0], out[1], out[2], out[3]};
    *(float4*)&d_feat[(size_t)pt * FEAT + off + o] = o4;
}

__global__ void pool_kernel() {
    int b = blockIdx.x, st = blockIdx.y;
    int c = threadIdx.x;
    float mx = -FLT_MAX, sm = 0.f;
    int n0 = st * 256;
    for (int n = n0; n < n0 + 256; n++) {
        float v = d_feat[(size_t)(b * N + n) * FEAT + c];
        mx = fmaxf(mx, v);
        sm += v;
    }
    d_poolmax[(b * 8 + st) * FEAT + c] = mx;
    d_poolsum[(b * 8 + st) * FEAT + c] = sm;
}

__global__ void head_kernel(const float* fc1_w, const float* fc1_b,
                            const float* ln1_g, const float* ln1_b,
                            const float* fc2_w, const float* fc2_b,
                            const float* ln2_g, const float* ln2_b,
                            float* out) {
    __shared__ float g[1024];
    __shared__ float h[512];
    __shared__ float red[256];
    __shared__ float red2[256];
    int b = blockIdx.x, tid = threadIdx.x;
    for (int c = tid; c < 512; c += 256) {
        float mx = -FLT_MAX, sm = 0.f;
        for (int st = 0; st < 8; st++) {
            mx = fmaxf(mx, d_poolmax[(b * 8 + st) * FEAT + c]);
            sm += d_poolsum[(b * 8 + st) * FEAT + c];
        }
        g[c] = mx;
        g[512 + c] = sm * (1.f / (float)N);
    }
    __syncthreads();
    for (int j = tid; j < 512; j += 256) {
        float acc = fc1_b[j];
        const float* wr = fc1_w + (size_t)j * 1024;
        for (int i = 0; i < 1024; i++) acc = fmaf(g[i], wr[i], acc);
        h[j] = acc;
    }
    __syncthreads();
    {
        float a = h[tid], bb = h[tid + 256];
        red[tid] = a + bb;
        red2[tid] = a * a + bb * bb;
    }
    __syncthreads();
    for (int s = 128; s > 0; s >>= 1) {
        if (tid < s) { red[tid] += red[tid + s]; red2[tid] += red2[tid + s]; }
        __syncthreads();
    }
    float mu = red[0] * (1.f / 512.f);
    float var = red2[0] * (1.f / 512.f) - mu * mu;
    float inv = rsqrtf(var + EPSV);
    __syncthreads();
    for (int j = tid; j < 512; j += 256)
        h[j] = fmaxf(0.f, (h[j] - mu) * inv * ln1_g[j] + ln1_b[j]);
    __syncthreads();
    float z = fc2_b[tid];
    {
        const float* wr = fc2_w + (size_t)tid * 512;
        for (int i = 0; i < 512; i++) z = fmaf(h[i], wr[i], z);
    }
    red[tid] = z;
    red2[tid] = z * z;
    __syncthreads();
    for (int s = 128; s > 0; s >>= 1) {
        if (tid < s) { red[tid] += red[tid + s]; red2[tid] += red2[tid + s]; }
        __syncthreads();
    }
    float mu2 = red[0] * (1.f / 256.f);
    float var2 = red2[0] * (1.f / 256.f) - mu2 * mu2;
    float inv2 = rsqrtf(var2 + EPSV);
    out[b * 256 + tid] = (z - mu2) * inv2 * ln2_g[tid] + ln2_b[tid];
}

// ---------------- launch ----------------

extern "C" void kernel_launch(void* const* d_in, const int* in_sizes, int n_in,
                              void* d_out, int out_size) {
    (void)in_sizes; (void)n_in; (void)out_size;
    const float* points = (const float*)d_in[0];
    const float* Wl[4]  = {(const float*)d_in[1], (const float*)d_in[4],
                           (const float*)d_in[7], (const float*)d_in[10]};
    const float* gl[4]  = {(const float*)d_in[2], (const float*)d_in[5],
                           (const float*)d_in[8], (const float*)d_in[11]};
    const float* bl[4]  = {(const float*)d_in[3], (const float*)d_in[6],
                           (const float*)d_in[9], (const float*)d_in[12]};
    const float* fc1_w = (const float*)d_in[13];
    const float* fc1_b = (const float*)d_in[14];
    const float* ln1_g = (const float*)d_in[15];
    const float* ln1_b = (const float*)d_in[16];
    const float* fc2_w = (const float*)d_in[17];
    const float* fc2_b = (const float*)d_in[18];
    const float* ln2_g = (const float*)d_in[19];
    const float* ln2_b = (const float*)d_in[20];

    const int Cs[4]     = {3, 64, 64, 128};
    const int Os[4]     = {64, 64, 128, 256};
    const int offin[4]  = {0, 0, 64, 128};
    const int offout[4] = {0, 64, 128, 256};
    const int NPAIRS = NB * (NB + 1) / 2;   // 136

    for (int l = 0; l < 4; l++) {
        const float* xin = (l == 0) ? points : nullptr;
        int stride = (l == 0) ? 3 : FEAT;
        int C = Cs[l], O = Os[l];

        if (l == 0) {
            zero_acc_kernel<<<1, 256>>>();
            dist3_kernel<<<dim3(B, N / 64), 256>>>(points);
        } else {
            xx_kernel<<<(PTS + 255) / 256, 256>>>(xin, stride, offin[l], C);
            dist_kernel<<<dim3(B, NPAIRS), 512>>>(xin, stride, offin[l], C);
        }
        select_kernel<<<PTS / 4, 128>>>();
        st_kernel<<<dim3(PTS / 64, O / 64), 256>>>(xin, stride, offin[l], C, O, Wl[l]);
        gather_kernel<<<PTS / 64, 256>>>(O);
        bn_kernel<<<1, O>>>(O, gl[l], bl[l]);
        apply_kernel<<<(PTS * O / 4 + 255) / 256, 256>>>(O, offout[l]);
    }

    pool_kernel<<<dim3(B, 8), 512>>>();
    head_kernel<<<B, 256>>>(fc1_w, fc1_b, ln1_g, ln1_b,
                            fc2_w, fc2_b, ln2_g, ln2_b, (float*)d_out);
}